// round 12
// baseline (speedup 1.0000x reference)
#include <cuda_runtime.h>
#include <cuda_fp16.h>
#include <math.h>
#include <stdint.h>

// Problem constants
#define Bz 4
#define Tz 2048
#define Cz 768
#define NHz 12
#define HDz 64
#define TOKz (Bz * Tz)   // 8192
#define QKVN 2304        // fused q|k|v output width

// fp16 intermediate: fused qkv GEMM output
__device__ __half g_qkvh[TOKz * QKVN];

// fp16 operands
__device__ __half g_xhi[TOKz * Cz];
__device__ __half g_veh[TOKz * Cz];
__device__ __half g_whi[4 * Cz * Cz];   // [Wq;Wk;Wv;Wproj]

// attention operands (q pre-scaled by 1.2*0.125*log2(e))
__device__ __half g_qh[TOKz * Cz];
__device__ __half g_kh[TOKz * Cz];
__device__ __half g_vh[TOKz * Cz];

// attention output (A operand of proj GEMM)
__device__ __half g_yh[TOKz * Cz];

// ---------------------------------------------------------------------------
// Helpers
// ---------------------------------------------------------------------------
__device__ __forceinline__ uint32_t smem_u32(const void* p) {
    uint32_t a;
    asm("{ .reg .u64 t; cvta.to.shared.u64 t, %1; cvt.u32.u64 %0, t; }"
        : "=r"(a) : "l"(p));
    return a;
}

__device__ __forceinline__ float exp2a(float x) {
    float y;
    asm("ex2.approx.f32 %0, %1;" : "=f"(y) : "f"(x));
    return y;
}

#define LDSM4(r, addr)                                                        \
    asm volatile("ldmatrix.sync.aligned.m8n8.x4.shared.b16 {%0,%1,%2,%3}, [%4];" \
                 : "=r"((r)[0]), "=r"((r)[1]), "=r"((r)[2]), "=r"((r)[3])     \
                 : "r"(addr))

#define LDSM4T(r, addr)                                                       \
    asm volatile("ldmatrix.sync.aligned.m8n8.x4.trans.shared.b16 {%0,%1,%2,%3}, [%4];" \
                 : "=r"((r)[0]), "=r"((r)[1]), "=r"((r)[2]), "=r"((r)[3])     \
                 : "r"(addr))

#define LDSM2(r, addr)                                                        \
    asm volatile("ldmatrix.sync.aligned.m8n8.x2.shared.b16 {%0,%1}, [%2];"    \
                 : "=r"((r)[0]), "=r"((r)[1]) : "r"(addr))

#define MMAH(c, a, b0, b1)                                                    \
    asm volatile("mma.sync.aligned.m16n8k16.row.col.f32.f16.f16.f32 "        \
                 "{%0,%1,%2,%3}, {%4,%5,%6,%7}, {%8,%9}, {%0,%1,%2,%3};"     \
                 : "+f"((c)[0]), "+f"((c)[1]), "+f"((c)[2]), "+f"((c)[3])    \
                 : "r"((a)[0]), "r"((a)[1]), "r"((a)[2]), "r"((a)[3]),       \
                   "r"(b0), "r"(b1))

#define CPASYNC16(s, g)                                                       \
    asm volatile("cp.async.ca.shared.global [%0], [%1], 16;" :: "r"(s), "l"(g))

__device__ __forceinline__ uint32_t packh2(float a, float b) {
    __half2 t = __floats2half2_rn(a, b);
    return *(uint32_t*)&t;
}

// ---------------------------------------------------------------------------
// fp16 HMMA GEMM (NT): C[M x N] = A * B^T, K=768.
// BM=256, BN=128, 512 threads (16 warps as 4m x 4n, warp tile 64x32), occ 1.
// Halves L2 traffic vs 128x128 tiling. HALFOUT: fp16 C.
// ---------------------------------------------------------------------------
#define GK 768
#define NCH 12
#define ARR_A 32768               // 256x64 fp16 swizzled
#define ARR_B 16384               // 128x64 fp16 swizzled
#define STG (ARR_A + ARR_B)       // 48 KB
#define GSMEM (2 * STG)           // 96 KB

template <int HALFOUT>
__global__ __launch_bounds__(512, 1) void gemm_mma(
    const __half* __restrict__ Ahi,
    const __half* __restrict__ Bh, void* __restrict__ Cout, int ldc)
{
    extern __shared__ __align__(1024) char dsm[];
    const uint32_t sb = smem_u32(dsm);
    const int tid = threadIdx.x;
    const int wid = tid >> 5, lane = tid & 31;
    const int bm = blockIdx.y << 8;   // 256-row tiles
    const int bn = blockIdx.x << 7;   // 128-col tiles
    const int warp_m = wid >> 2;      // 0..3
    const int warp_n = wid & 3;       // 0..3

    const __half* gA0 = Ahi + (size_t)bm * GK;
    const __half* gB  = Bh  + (size_t)bn * GK;

    const int c16 = tid & 7;

    float acc[4][4][4];
#pragma unroll
    for (int i = 0; i < 4; i++)
#pragma unroll
        for (int j = 0; j < 4; j++)
#pragma unroll
            for (int k = 0; k < 4; k++) acc[i][j][k] = 0.f;

    auto issue = [&](int c, int s) {
        uint32_t sbase = sb + s * STG;
        // A: 256 rows x 8 chunks = 2048 segs, 4 per thread
#pragma unroll
        for (int i = 0; i < 4; i++) {
            int row = (i * 512 + tid) >> 3;
            uint32_t so = (uint32_t)(row * 128 + c16 * 16) ^ (uint32_t)((row & 7) << 4);
            size_t go = (size_t)row * GK + c * 64 + c16 * 8;
            CPASYNC16(sbase + so, (const char*)(gA0 + go));
        }
        // B: 128 rows x 8 chunks = 1024 segs, 2 per thread
#pragma unroll
        for (int i = 0; i < 2; i++) {
            int row = (i * 512 + tid) >> 3;
            uint32_t so = (uint32_t)(row * 128 + c16 * 16) ^ (uint32_t)((row & 7) << 4);
            size_t go = (size_t)row * GK + c * 64 + c16 * 8;
            CPASYNC16(sbase + ARR_A + so, (const char*)(gB + go));
        }
        asm volatile("cp.async.commit_group;");
    };

    issue(0, 0);

    const uint32_t aswz = (uint32_t)((lane & 7) << 4);
    const int arow = warp_m * 64 + (lane & 15);
    const int brow = warp_n * 32 + (lane & 7);
    const uint32_t akhi = (uint32_t)((lane >> 4) << 4);
    const uint32_t bkhi = (uint32_t)(((lane >> 3) & 1) << 4);

#pragma unroll 1
    for (int c = 0; c < NCH; ++c) {
        if (c + 1 < NCH) {
            issue(c + 1, (c + 1) & 1);
            asm volatile("cp.async.wait_group 1;");
        } else {
            asm volatile("cp.async.wait_group 0;");
        }
        __syncthreads();

        const uint32_t sbase = sb + (c & 1) * STG;
#pragma unroll
        for (int ks = 0; ks < 4; ++ks) {
            uint32_t ah[4][4], bh[4][2];
            const uint32_t ak = ((uint32_t)(ks * 32) + akhi) ^ aswz;
            const uint32_t bk = ((uint32_t)(ks * 32) + bkhi) ^ aswz;
#pragma unroll
            for (int mt = 0; mt < 4; mt++) {
                uint32_t ra = sbase + (uint32_t)((arow + mt * 16) * 128) + ak;
                LDSM4(ah[mt], ra);
            }
#pragma unroll
            for (int nt = 0; nt < 4; nt++) {
                uint32_t rb = sbase + ARR_A + (uint32_t)((brow + nt * 8) * 128) + bk;
                LDSM2(bh[nt], rb);
            }
#pragma unroll
            for (int mt = 0; mt < 4; mt++)
#pragma unroll
                for (int nt = 0; nt < 4; nt++)
                    MMAH(acc[mt][nt], ah[mt], bh[nt][0], bh[nt][1]);
        }
        __syncthreads();
    }

    const int crow = bm + warp_m * 64 + (lane >> 2);
    const int ccol = bn + warp_n * 32 + (lane & 3) * 2;
    if (HALFOUT) {
        __half* C = (__half*)Cout;
#pragma unroll
        for (int mt = 0; mt < 4; mt++)
#pragma unroll
            for (int nt = 0; nt < 4; nt++) {
                __half* p0 = C + (size_t)(crow + mt * 16) * ldc + ccol + nt * 8;
                __half* p1 = p0 + 8 * ldc;
                *(__half2*)p0 = __floats2half2_rn(acc[mt][nt][0], acc[mt][nt][1]);
                *(__half2*)p1 = __floats2half2_rn(acc[mt][nt][2], acc[mt][nt][3]);
            }
    } else {
        float* C = (float*)Cout;
#pragma unroll
        for (int mt = 0; mt < 4; mt++)
#pragma unroll
            for (int nt = 0; nt < 4; nt++) {
                float* p0 = C + (size_t)(crow + mt * 16) * ldc + ccol + nt * 8;
                float* p1 = p0 + 8 * ldc;
                *(float2*)p0 = make_float2(acc[mt][nt][0], acc[mt][nt][1]);
                *(float2*)p1 = make_float2(acc[mt][nt][2], acc[mt][nt][3]);
            }
    }
}

// ---------------------------------------------------------------------------
// Fused fp32 -> fp16 convert: x, ve, then 4 weight matrices
// ---------------------------------------------------------------------------
__global__ void cvt_all(const float4* __restrict__ x, const float4* __restrict__ ve,
                        const float4* __restrict__ w0, const float4* __restrict__ w1,
                        const float4* __restrict__ w2, const float4* __restrict__ w3,
                        __half* __restrict__ xhi, __half* __restrict__ veh,
                        __half* __restrict__ whi, int n4x, int n4w)
{
    int i = blockIdx.x * 256 + threadIdx.x;
    const float4* src;
    __half* dst;
    int r;
    if (i < n4x) {
        src = x; dst = xhi; r = i;
    } else if (i < 2 * n4x) {
        src = ve; dst = veh; r = i - n4x;
    } else {
        int j = i - 2 * n4x;
        int m = j / n4w;
        if (m >= 4) return;
        r = j - m * n4w;
        src = (m == 0) ? w0 : (m == 1) ? w1 : (m == 2) ? w2 : w3;
        dst = whi + (size_t)m * (Cz * Cz);
    }
    float4 v = src[r];
    ((__half2*)dst)[2 * r]     = __half2(__float2half(v.x), __float2half(v.y));
    ((__half2*)dst)[2 * r + 1] = __half2(__float2half(v.z), __float2half(v.w));
}

// ---------------------------------------------------------------------------
// RoPE + RMSNorm + gated ve add; q scale = 1.2 * 0.125 * log2(e)
// ---------------------------------------------------------------------------
#define QSCALE 0.21640425613334451f   // 0.15 * log2(e)

__global__ __launch_bounds__(384) void rope_rms_gate_kernel(
    const float* __restrict__ x,
    const float* __restrict__ cosb, const float* __restrict__ sinb,
    const float* __restrict__ Wg)
{
    const int tok = blockIdx.x;
    const int t = tok & (Tz - 1);
    const int h = threadIdx.x >> 5;
    const int lane = threadIdx.x & 31;
    const size_t qkvbase = (size_t)tok * QKVN + h * HDz;
    const size_t base = (size_t)tok * Cz + h * HDz;

    const float cv = cosb[t * 32 + lane];
    const float sv = sinb[t * 32 + lane];

    {   // q: rope + rms (* QSCALE)
        float x1 = __half2float(g_qkvh[qkvbase + lane]);
        float x2 = __half2float(g_qkvh[qkvbase + 32 + lane]);
        float r1 = x1 * cv - x2 * sv;
        float r2 = x1 * sv + x2 * cv;
        float ss = r1 * r1 + r2 * r2;
#pragma unroll
        for (int o = 16; o > 0; o >>= 1) ss += __shfl_xor_sync(0xFFFFFFFFu, ss, o);
        float inv = rsqrtf(ss * (1.0f / 64.0f) + 1e-6f) * QSCALE;
        g_qh[base + lane] = __float2half(r1 * inv);
        g_qh[base + 32 + lane] = __float2half(r2 * inv);
    }
    {   // k: rope + rms (* 1.2)
        float x1 = __half2float(g_qkvh[qkvbase + Cz + lane]);
        float x2 = __half2float(g_qkvh[qkvbase + Cz + 32 + lane]);
        float r1 = x1 * cv - x2 * sv;
        float r2 = x1 * sv + x2 * cv;
        float ss = r1 * r1 + r2 * r2;
#pragma unroll
        for (int o = 16; o > 0; o >>= 1) ss += __shfl_xor_sync(0xFFFFFFFFu, ss, o);
        float inv = rsqrtf(ss * (1.0f / 64.0f) + 1e-6f) * 1.2f;
        g_kh[base + lane] = __float2half(r1 * inv);
        g_kh[base + 32 + lane] = __float2half(r2 * inv);
    }
    {   // v: gated ve add
        float p = (lane < 12) ? x[(size_t)tok * Cz + lane] * Wg[h * 12 + lane] : 0.f;
#pragma unroll
        for (int o = 16; o > 0; o >>= 1) p += __shfl_xor_sync(0xFFFFFFFFu, p, o);
        float gate = 3.0f / (1.0f + __expf(-p));
        float v1 = __half2float(g_qkvh[qkvbase + 2 * Cz + lane])
                 + gate * __half2float(g_veh[base + lane]);
        float v2 = __half2float(g_qkvh[qkvbase + 2 * Cz + 32 + lane])
                 + gate * __half2float(g_veh[base + 32 + lane]);
        g_vh[base + lane] = __float2half(v1);
        g_vh[base + 32 + lane] = __float2half(v2);
    }
}

// ---------------------------------------------------------------------------
// MMA flash attention, 64-query CTA (4 warps, occ 4), sliding window.
// S in log2 domain (scale folded into q); exp2 softmax.
// smem: Q 8K | 2 stages of (K 8K + V 8K) = 40 KB.
// ---------------------------------------------------------------------------
#define ATT_QH 0
#define ATT_K  8192
#define ATT_STG 16384
#define ATT_SMEM (8192 + 2 * ATT_STG)   // 40960

__global__ __launch_bounds__(128, 4) void attn_mma(const int* __restrict__ winp)
{
    extern __shared__ __align__(1024) char dsm[];
    const uint32_t sb = smem_u32(dsm);
    const int tid = threadIdx.x;
    const int wid = tid >> 5, lane = tid & 31;
    const int qt0 = (gridDim.x - 1 - blockIdx.x) * 64;   // longest-first
    const int h = blockIdx.y;
    const int b = blockIdx.z;
    const int W = *winp;

    const size_t hoff = (size_t)h * HDz;
    const size_t btok = (size_t)b * Tz;

    // ---- load Q
    {
#pragma unroll
        for (int i = 0; i < 4; i++) {
            int row = (i * 128 + tid) >> 3;
            int c16 = tid & 7;
            uint32_t so = (uint32_t)(row * 128 + c16 * 16) ^ (uint32_t)((row & 7) << 4);
            size_t go = (btok + qt0 + row) * Cz + hoff + c16 * 8;
            CPASYNC16(sb + ATT_QH + so, (const char*)(g_qh + go));
        }
        asm volatile("cp.async.commit_group;");
    }

    auto issue_kv = [&](int kt0, int s) {
        uint32_t sbase = sb + ATT_K + s * ATT_STG;
#pragma unroll
        for (int i = 0; i < 4; i++) {
            int row = (i * 128 + tid) >> 3;
            int c16 = tid & 7;
            uint32_t so = (uint32_t)(row * 128 + c16 * 16) ^ (uint32_t)((row & 7) << 4);
            size_t go = (btok + kt0 + row) * Cz + hoff + c16 * 8;
            CPASYNC16(sbase + so,        (const char*)(g_kh + go));
            CPASYNC16(sbase + 8192 + so, (const char*)(g_vh + go));
        }
        asm volatile("cp.async.commit_group;");
    };

    int lo = qt0 - W; if (lo < 0) lo = 0;
    const int kt_begin = lo & ~63;
    const int nt = ((qt0 - kt_begin) >> 6) + 1;

    issue_kv(kt_begin, 0);

    const int arow = wid * 16 + (lane & 15);
    const uint32_t aswzQ = (uint32_t)((arow & 7) << 4);
    const uint32_t acol_hi = (uint32_t)((lane >> 4) << 4);

    const int r0 = qt0 + wid * 16 + (lane >> 2);
    const int r1 = r0 + 8;
    const int cbase = (lane & 3) * 2;

    float m0 = -1e30f, m1 = -1e30f, l0 = 0.f, l1 = 0.f;
    float o[8][4];
#pragma unroll
    for (int j = 0; j < 8; j++)
#pragma unroll
        for (int q = 0; q < 4; q++) o[j][q] = 0.f;

#pragma unroll 1
    for (int it = 0; it < nt; ++it) {
        const int kt0 = kt_begin + it * 64;
        if (it + 1 < nt) {
            issue_kv(kt0 + 64, (it + 1) & 1);
            asm volatile("cp.async.wait_group 1;");
        } else {
            asm volatile("cp.async.wait_group 0;");
        }
        __syncthreads();

        const uint32_t kvb = sb + ATT_K + (it & 1) * ATT_STG;

        // ---- S = Q K^T (log2 domain)
        float sa[8][4];
#pragma unroll
        for (int j = 0; j < 8; j++)
#pragma unroll
            for (int q = 0; q < 4; q++) sa[j][q] = 0.f;

#pragma unroll
        for (int kk = 0; kk < 4; ++kk) {
            uint32_t ah[4];
            {
                uint32_t bc = ((uint32_t)(kk * 32) + acol_hi) ^ aswzQ;
                uint32_t ra = sb + ATT_QH + (uint32_t)(arow * 128) + bc;
                LDSM4(ah, ra);
            }
            uint32_t kh[4][4];
            {
                const int grp = lane >> 3;
                const int krow_off = (grp >> 1) * 8 + (lane & 7);
                const uint32_t bc_off = (uint32_t)(kk * 32 + (grp & 1) * 16);
#pragma unroll
                for (int p = 0; p < 4; p++) {
                    int krow = p * 16 + krow_off;
                    uint32_t so = (uint32_t)(krow * 128) + (bc_off ^ ((uint32_t)(krow & 7) << 4));
                    LDSM4(kh[p], kvb + so);
                }
            }
#pragma unroll
            for (int p = 0; p < 4; p++) {
                MMAH(sa[2 * p],     ah, kh[p][0], kh[p][1]);
                MMAH(sa[2 * p + 1], ah, kh[p][2], kh[p][3]);
            }
        }

        // ---- online softmax (base-2); interior tiles skip masking
        const bool full = (kt0 + 63 <= qt0) && (qt0 + 63 - kt0 <= W);
        float rm0 = -1e30f, rm1 = -1e30f;
        if (full) {
#pragma unroll
            for (int j = 0; j < 8; j++) {
                rm0 = fmaxf(rm0, fmaxf(sa[j][0], sa[j][1]));
                rm1 = fmaxf(rm1, fmaxf(sa[j][2], sa[j][3]));
            }
        } else {
#pragma unroll
            for (int j = 0; j < 8; j++) {
                const int c0 = kt0 + j * 8 + cbase;
                const int c1 = c0 + 1;
                bool ok00 = (c0 <= r0) && (r0 - c0 <= W);
                bool ok01 = (c1 <= r0) && (r0 - c1 <= W);
                bool ok10 = (c0 <= r1) && (r1 - c0 <= W);
                bool ok11 = (c1 <= r1) && (r1 - c1 <= W);
                sa[j][0] = ok00 ? sa[j][0] : -1e30f;
                sa[j][1] = ok01 ? sa[j][1] : -1e30f;
                sa[j][2] = ok10 ? sa[j][2] : -1e30f;
                sa[j][3] = ok11 ? sa[j][3] : -1e30f;
                rm0 = fmaxf(rm0, fmaxf(sa[j][0], sa[j][1]));
                rm1 = fmaxf(rm1, fmaxf(sa[j][2], sa[j][3]));
            }
        }
#pragma unroll
        for (int off = 1; off <= 2; off <<= 1) {
            rm0 = fmaxf(rm0, __shfl_xor_sync(0xFFFFFFFFu, rm0, off));
            rm1 = fmaxf(rm1, __shfl_xor_sync(0xFFFFFFFFu, rm1, off));
        }
        const float mn0 = fmaxf(m0, rm0);
        const float mn1 = fmaxf(m1, rm1);
        const float corr0 = exp2a(m0 - mn0);
        const float corr1 = exp2a(m1 - mn1);
        m0 = mn0; m1 = mn1;

        float rs0 = 0.f, rs1 = 0.f;
        uint32_t aph[4][4];
        if (full) {
#pragma unroll
            for (int p = 0; p < 4; p++) {
#pragma unroll
                for (int jl = 0; jl < 2; jl++) {
                    const int j = 2 * p + jl;
                    float p0 = exp2a(sa[j][0] - mn0);
                    float p1 = exp2a(sa[j][1] - mn0);
                    float p2 = exp2a(sa[j][2] - mn1);
                    float p3 = exp2a(sa[j][3] - mn1);
                    rs0 += p0 + p1;
                    rs1 += p2 + p3;
                    aph[p][2 * jl + 0] = packh2(p0, p1);
                    aph[p][2 * jl + 1] = packh2(p2, p3);
                }
            }
        } else {
#pragma unroll
            for (int p = 0; p < 4; p++) {
#pragma unroll
                for (int jl = 0; jl < 2; jl++) {
                    const int j = 2 * p + jl;
                    float p0 = (sa[j][0] > -1e29f) ? exp2a(sa[j][0] - mn0) : 0.f;
                    float p1 = (sa[j][1] > -1e29f) ? exp2a(sa[j][1] - mn0) : 0.f;
                    float p2 = (sa[j][2] > -1e29f) ? exp2a(sa[j][2] - mn1) : 0.f;
                    float p3 = (sa[j][3] > -1e29f) ? exp2a(sa[j][3] - mn1) : 0.f;
                    rs0 += p0 + p1;
                    rs1 += p2 + p3;
                    aph[p][2 * jl + 0] = packh2(p0, p1);
                    aph[p][2 * jl + 1] = packh2(p2, p3);
                }
            }
        }
#pragma unroll
        for (int off = 1; off <= 2; off <<= 1) {
            rs0 += __shfl_xor_sync(0xFFFFFFFFu, rs0, off);
            rs1 += __shfl_xor_sync(0xFFFFFFFFu, rs1, off);
        }
        l0 = l0 * corr0 + rs0;
        l1 = l1 * corr1 + rs1;

#pragma unroll
        for (int j = 0; j < 8; j++) {
            o[j][0] *= corr0; o[j][1] *= corr0;
            o[j][2] *= corr1; o[j][3] *= corr1;
        }

        // ---- O += P V
        const uint32_t vbase = kvb + 8192;
        {
            const int vrow_off = lane & 15;
            const uint32_t vcol_hi = (uint32_t)((lane >> 4) << 4);
#pragma unroll
            for (int kk = 0; kk < 4; ++kk) {
                uint32_t vh[4][4];
#pragma unroll
                for (int t = 0; t < 4; t++) {
                    int vrow = kk * 16 + vrow_off;
                    uint32_t bc = ((uint32_t)(t * 32) + vcol_hi) ^ ((uint32_t)(vrow & 7) << 4);
                    LDSM4T(vh[t], vbase + (uint32_t)(vrow * 128) + bc);
                }
#pragma unroll
                for (int t = 0; t < 4; t++) {
                    MMAH(o[2 * t],     aph[kk], vh[t][0], vh[t][1]);
                    MMAH(o[2 * t + 1], aph[kk], vh[t][2], vh[t][3]);
                }
            }
        }
        __syncthreads();
    }

    // epilogue: normalize, write fp16 y
    const float i0 = 1.0f / l0;
    const float i1 = 1.0f / l1;
#pragma unroll
    for (int j = 0; j < 8; j++) {
        size_t col = hoff + j * 8 + cbase;
        size_t idx0 = (btok + r0) * Cz + col;
        size_t idx1 = (btok + r1) * Cz + col;
        *(__half2*)(g_yh + idx0) = __floats2half2_rn(o[j][0] * i0, o[j][1] * i0);
        *(__half2*)(g_yh + idx1) = __floats2half2_rn(o[j][2] * i1, o[j][3] * i1);
    }
}

// ---------------------------------------------------------------------------
extern "C" void kernel_launch(void* const* d_in, const int* in_sizes, int n_in,
                              void* d_out, int out_size)
{
    const float* x     = (const float*)d_in[0];
    const float* ve    = (const float*)d_in[1];
    const float* cosb  = (const float*)d_in[2];
    const float* sinb  = (const float*)d_in[3];
    const float* Wq    = (const float*)d_in[4];
    const float* Wk    = (const float*)d_in[5];
    const float* Wv    = (const float*)d_in[6];
    const float* Wproj = (const float*)d_in[7];
    const float* Wg    = (const float*)d_in[8];
    const int*   win   = (const int*)d_in[9];
    float* out = (float*)d_out;

    __half *qkvh, *xhi, *veh, *whi, *yh;
    cudaGetSymbolAddress((void**)&qkvh, g_qkvh);
    cudaGetSymbolAddress((void**)&xhi, g_xhi);
    cudaGetSymbolAddress((void**)&veh, g_veh);
    cudaGetSymbolAddress((void**)&whi, g_whi);
    cudaGetSymbolAddress((void**)&yh, g_yh);

    const int WW = Cz * Cz;
    const int n4x = TOKz * Cz / 4;
    const int n4w = WW / 4;
    const int n4tot = 2 * n4x + 4 * n4w;

    cvt_all<<<(n4tot + 255) / 256, 256>>>((const float4*)x, (const float4*)ve,
                                          (const float4*)Wq, (const float4*)Wk,
                                          (const float4*)Wv, (const float4*)Wproj,
                                          xhi, veh, whi, n4x, n4w);

    cudaFuncSetAttribute((const void*)gemm_mma<1>,
                         cudaFuncAttributeMaxDynamicSharedMemorySize, GSMEM);
    cudaFuncSetAttribute((const void*)gemm_mma<0>,
                         cudaFuncAttributeMaxDynamicSharedMemorySize, GSMEM);

    // fused QKV GEMM (fp16 out): B = [Wq;Wk;Wv], N = 2304, BM=256
    gemm_mma<1><<<dim3(QKVN / 128, TOKz / 256), 512, GSMEM>>>(xhi, whi, qkvh, QKVN);

    rope_rms_gate_kernel<<<TOKz, 384>>>(x, cosb, sinb, Wg);

    cudaFuncSetAttribute(attn_mma, cudaFuncAttributeMaxDynamicSharedMemorySize, ATT_SMEM);
    attn_mma<<<dim3(Tz / 64, NHz, Bz), 128, ATT_SMEM>>>(win);

    // projection GEMM (fp32 out): A = y, B = Wproj
    gemm_mma<0><<<dim3(Cz / 128, TOKz / 256), 512, GSMEM>>>(yh, whi + 3 * WW, out, Cz);
}

// round 13
// speedup vs baseline: 1.0625x; 1.0625x over previous
#include <cuda_runtime.h>
#include <cuda_fp16.h>
#include <math.h>
#include <stdint.h>

// Problem constants
#define Bz 4
#define Tz 2048
#define Cz 768
#define NHz 12
#define HDz 64
#define TOKz (Bz * Tz)   // 8192
#define QKVN 2304        // fused q|k|v output width

// fp16 intermediate: fused qkv GEMM output
__device__ __half g_qkvh[TOKz * QKVN];

// fp16 operands
__device__ __half g_xhi[TOKz * Cz];
__device__ __half g_veh[TOKz * Cz];
__device__ __half g_whi[4 * Cz * Cz];   // [Wq;Wk;Wv;Wproj]

// attention operands (q pre-scaled by 1.2*0.125*log2(e))
__device__ __half g_qh[TOKz * Cz];
__device__ __half g_kh[TOKz * Cz];
__device__ __half g_vh[TOKz * Cz];

// attention output (A operand of proj GEMM)
__device__ __half g_yh[TOKz * Cz];

// ---------------------------------------------------------------------------
// Helpers
// ---------------------------------------------------------------------------
__device__ __forceinline__ uint32_t smem_u32(const void* p) {
    uint32_t a;
    asm("{ .reg .u64 t; cvta.to.shared.u64 t, %1; cvt.u32.u64 %0, t; }"
        : "=r"(a) : "l"(p));
    return a;
}

__device__ __forceinline__ float exp2a(float x) {
    float y;
    asm("ex2.approx.f32 %0, %1;" : "=f"(y) : "f"(x));
    return y;
}

#define LDSM4(r, addr)                                                        \
    asm volatile("ldmatrix.sync.aligned.m8n8.x4.shared.b16 {%0,%1,%2,%3}, [%4];" \
                 : "=r"((r)[0]), "=r"((r)[1]), "=r"((r)[2]), "=r"((r)[3])     \
                 : "r"(addr))

#define LDSM4T(r, addr)                                                       \
    asm volatile("ldmatrix.sync.aligned.m8n8.x4.trans.shared.b16 {%0,%1,%2,%3}, [%4];" \
                 : "=r"((r)[0]), "=r"((r)[1]), "=r"((r)[2]), "=r"((r)[3])     \
                 : "r"(addr))

#define LDSM2(r, addr)                                                        \
    asm volatile("ldmatrix.sync.aligned.m8n8.x2.shared.b16 {%0,%1}, [%2];"    \
                 : "=r"((r)[0]), "=r"((r)[1]) : "r"(addr))

#define MMAH(c, a, b0, b1)                                                    \
    asm volatile("mma.sync.aligned.m16n8k16.row.col.f32.f16.f16.f32 "        \
                 "{%0,%1,%2,%3}, {%4,%5,%6,%7}, {%8,%9}, {%0,%1,%2,%3};"     \
                 : "+f"((c)[0]), "+f"((c)[1]), "+f"((c)[2]), "+f"((c)[3])    \
                 : "r"((a)[0]), "r"((a)[1]), "r"((a)[2]), "r"((a)[3]),       \
                   "r"(b0), "r"(b1))

#define CPASYNC16(s, g)                                                       \
    asm volatile("cp.async.ca.shared.global [%0], [%1], 16;" :: "r"(s), "l"(g))

__device__ __forceinline__ uint32_t packh2(float a, float b) {
    __half2 t = __floats2half2_rn(a, b);
    return *(uint32_t*)&t;
}

// ---------------------------------------------------------------------------
// fp16 HMMA GEMM (NT): C[M x N] = A * B^T, K=768, hi-only.
// Block 128x128, 256 thr (8 warps 2m x 4n, warp tile 64x32), occ 2 (R11 cfg).
// HALFOUT: write C as fp16 (else fp32).
// ---------------------------------------------------------------------------
#define GK 768
#define NCH 12
#define ARR 16384                 // one 128x64 fp16 array (swizzled)
#define STG2 (2 * ARR)            // A, B = 32 KB
#define GSMEM (2 * STG2)          // 64 KB

template <int HALFOUT>
__global__ __launch_bounds__(256, 2) void gemm_mma(
    const __half* __restrict__ Ahi,
    const __half* __restrict__ Bh, void* __restrict__ Cout, int ldc)
{
    extern __shared__ __align__(1024) char dsm[];
    const uint32_t sb = smem_u32(dsm);
    const int tid = threadIdx.x;
    const int wid = tid >> 5, lane = tid & 31;
    const int bm = blockIdx.y << 7;
    const int bn = blockIdx.x << 7;
    const int warp_m = wid >> 2;
    const int warp_n = wid & 3;

    const __half* gA0 = Ahi + (size_t)bm * GK;
    const __half* gB  = Bh  + (size_t)bn * GK;

    const int lrow = tid >> 3;
    const int lc16 = tid & 7;

    float acc[4][4][4];
#pragma unroll
    for (int i = 0; i < 4; i++)
#pragma unroll
        for (int j = 0; j < 4; j++)
#pragma unroll
            for (int k = 0; k < 4; k++) acc[i][j][k] = 0.f;

    auto issue = [&](int c, int s) {
        uint32_t sbase = sb + s * STG2;
#pragma unroll
        for (int i = 0; i < 4; i++) {
            int row = lrow + i * 32;
            uint32_t so = (uint32_t)(row * 128 + lc16 * 16) ^ (uint32_t)((row & 7) << 4);
            size_t go = (size_t)row * GK + c * 64 + lc16 * 8;
            CPASYNC16(sbase + so,       (const char*)(gA0 + go));
            CPASYNC16(sbase + ARR + so, (const char*)(gB + go));
        }
        asm volatile("cp.async.commit_group;");
    };

    issue(0, 0);

    const uint32_t aswz = (uint32_t)((lane & 7) << 4);
    const int arow = warp_m * 64 + (lane & 15);
    const int brow = warp_n * 32 + (lane & 7);
    const uint32_t akhi = (uint32_t)((lane >> 4) << 4);
    const uint32_t bkhi = (uint32_t)(((lane >> 3) & 1) << 4);

#pragma unroll 1
    for (int c = 0; c < NCH; ++c) {
        if (c + 1 < NCH) {
            issue(c + 1, (c + 1) & 1);
            asm volatile("cp.async.wait_group 1;");
        } else {
            asm volatile("cp.async.wait_group 0;");
        }
        __syncthreads();

        const uint32_t sbase = sb + (c & 1) * STG2;
#pragma unroll
        for (int ks = 0; ks < 4; ++ks) {
            uint32_t ah[4][4], bh[4][2];
            const uint32_t ak = ((uint32_t)(ks * 32) + akhi) ^ aswz;
            const uint32_t bk = ((uint32_t)(ks * 32) + bkhi) ^ aswz;
#pragma unroll
            for (int mt = 0; mt < 4; mt++) {
                uint32_t ra = sbase + (uint32_t)((arow + mt * 16) * 128) + ak;
                LDSM4(ah[mt], ra);
            }
#pragma unroll
            for (int nt = 0; nt < 4; nt++) {
                uint32_t rb = sbase + ARR + (uint32_t)((brow + nt * 8) * 128) + bk;
                LDSM2(bh[nt], rb);
            }
#pragma unroll
            for (int mt = 0; mt < 4; mt++)
#pragma unroll
                for (int nt = 0; nt < 4; nt++)
                    MMAH(acc[mt][nt], ah[mt], bh[nt][0], bh[nt][1]);
        }
        __syncthreads();
    }

    const int crow = bm + warp_m * 64 + (lane >> 2);
    const int ccol = bn + warp_n * 32 + (lane & 3) * 2;
    if (HALFOUT) {
        __half* C = (__half*)Cout;
#pragma unroll
        for (int mt = 0; mt < 4; mt++)
#pragma unroll
            for (int nt = 0; nt < 4; nt++) {
                __half* p0 = C + (size_t)(crow + mt * 16) * ldc + ccol + nt * 8;
                __half* p1 = p0 + 8 * ldc;
                *(__half2*)p0 = __floats2half2_rn(acc[mt][nt][0], acc[mt][nt][1]);
                *(__half2*)p1 = __floats2half2_rn(acc[mt][nt][2], acc[mt][nt][3]);
            }
    } else {
        float* C = (float*)Cout;
#pragma unroll
        for (int mt = 0; mt < 4; mt++)
#pragma unroll
            for (int nt = 0; nt < 4; nt++) {
                float* p0 = C + (size_t)(crow + mt * 16) * ldc + ccol + nt * 8;
                float* p1 = p0 + 8 * ldc;
                *(float2*)p0 = make_float2(acc[mt][nt][0], acc[mt][nt][1]);
                *(float2*)p1 = make_float2(acc[mt][nt][2], acc[mt][nt][3]);
            }
    }
}

// ---------------------------------------------------------------------------
// Fused fp32 -> fp16 convert: x, ve, then 4 weight matrices
// ---------------------------------------------------------------------------
__global__ void cvt_all(const float4* __restrict__ x, const float4* __restrict__ ve,
                        const float4* __restrict__ w0, const float4* __restrict__ w1,
                        const float4* __restrict__ w2, const float4* __restrict__ w3,
                        __half* __restrict__ xhi, __half* __restrict__ veh,
                        __half* __restrict__ whi, int n4x, int n4w)
{
    int i = blockIdx.x * 256 + threadIdx.x;
    const float4* src;
    __half* dst;
    int r;
    if (i < n4x) {
        src = x; dst = xhi; r = i;
    } else if (i < 2 * n4x) {
        src = ve; dst = veh; r = i - n4x;
    } else {
        int j = i - 2 * n4x;
        int m = j / n4w;
        if (m >= 4) return;
        r = j - m * n4w;
        src = (m == 0) ? w0 : (m == 1) ? w1 : (m == 2) ? w2 : w3;
        dst = whi + (size_t)m * (Cz * Cz);
    }
    float4 v = src[r];
    ((__half2*)dst)[2 * r]     = __half2(__float2half(v.x), __float2half(v.y));
    ((__half2*)dst)[2 * r + 1] = __half2(__float2half(v.z), __float2half(v.w));
}

// ---------------------------------------------------------------------------
// RoPE + RMSNorm + gated ve add; q scale = 1.2 * 0.125 * log2(e)
// ---------------------------------------------------------------------------
#define QSCALE 0.21640425613334451f   // 0.15 * log2(e)

__global__ __launch_bounds__(384) void rope_rms_gate_kernel(
    const float* __restrict__ x,
    const float* __restrict__ cosb, const float* __restrict__ sinb,
    const float* __restrict__ Wg)
{
    const int tok = blockIdx.x;
    const int t = tok & (Tz - 1);
    const int h = threadIdx.x >> 5;
    const int lane = threadIdx.x & 31;
    const size_t qkvbase = (size_t)tok * QKVN + h * HDz;
    const size_t base = (size_t)tok * Cz + h * HDz;

    const float cv = cosb[t * 32 + lane];
    const float sv = sinb[t * 32 + lane];

    {   // q: rope + rms (* QSCALE)
        float x1 = __half2float(g_qkvh[qkvbase + lane]);
        float x2 = __half2float(g_qkvh[qkvbase + 32 + lane]);
        float r1 = x1 * cv - x2 * sv;
        float r2 = x1 * sv + x2 * cv;
        float ss = r1 * r1 + r2 * r2;
#pragma unroll
        for (int o = 16; o > 0; o >>= 1) ss += __shfl_xor_sync(0xFFFFFFFFu, ss, o);
        float inv = rsqrtf(ss * (1.0f / 64.0f) + 1e-6f) * QSCALE;
        g_qh[base + lane] = __float2half(r1 * inv);
        g_qh[base + 32 + lane] = __float2half(r2 * inv);
    }
    {   // k: rope + rms (* 1.2)
        float x1 = __half2float(g_qkvh[qkvbase + Cz + lane]);
        float x2 = __half2float(g_qkvh[qkvbase + Cz + 32 + lane]);
        float r1 = x1 * cv - x2 * sv;
        float r2 = x1 * sv + x2 * cv;
        float ss = r1 * r1 + r2 * r2;
#pragma unroll
        for (int o = 16; o > 0; o >>= 1) ss += __shfl_xor_sync(0xFFFFFFFFu, ss, o);
        float inv = rsqrtf(ss * (1.0f / 64.0f) + 1e-6f) * 1.2f;
        g_kh[base + lane] = __float2half(r1 * inv);
        g_kh[base + 32 + lane] = __float2half(r2 * inv);
    }
    {   // v: gated ve add
        float p = (lane < 12) ? x[(size_t)tok * Cz + lane] * Wg[h * 12 + lane] : 0.f;
#pragma unroll
        for (int o = 16; o > 0; o >>= 1) p += __shfl_xor_sync(0xFFFFFFFFu, p, o);
        float gate = 3.0f / (1.0f + __expf(-p));
        float v1 = __half2float(g_qkvh[qkvbase + 2 * Cz + lane])
                 + gate * __half2float(g_veh[base + lane]);
        float v2 = __half2float(g_qkvh[qkvbase + 2 * Cz + 32 + lane])
                 + gate * __half2float(g_veh[base + 32 + lane]);
        g_vh[base + lane] = __float2half(v1);
        g_vh[base + 32 + lane] = __float2half(v2);
    }
}

// ---------------------------------------------------------------------------
// MMA flash attention, 64-query CTA (4 warps, occ 4), sliding window.
// S in log2 domain (scale folded into q); exp2 softmax.
// smem: Q 8K | 2 stages of (K 8K + V 8K) = 40 KB.
// ---------------------------------------------------------------------------
#define ATT_QH 0
#define ATT_K  8192
#define ATT_STG 16384
#define ATT_SMEM (8192 + 2 * ATT_STG)   // 40960

__global__ __launch_bounds__(128, 4) void attn_mma(const int* __restrict__ winp)
{
    extern __shared__ __align__(1024) char dsm[];
    const uint32_t sb = smem_u32(dsm);
    const int tid = threadIdx.x;
    const int wid = tid >> 5, lane = tid & 31;
    const int qt0 = (gridDim.x - 1 - blockIdx.x) * 64;   // longest-first
    const int h = blockIdx.y;
    const int b = blockIdx.z;
    const int W = *winp;

    const size_t hoff = (size_t)h * HDz;
    const size_t btok = (size_t)b * Tz;

    // ---- load Q
    {
#pragma unroll
        for (int i = 0; i < 4; i++) {
            int row = (i * 128 + tid) >> 3;
            int c16 = tid & 7;
            uint32_t so = (uint32_t)(row * 128 + c16 * 16) ^ (uint32_t)((row & 7) << 4);
            size_t go = (btok + qt0 + row) * Cz + hoff + c16 * 8;
            CPASYNC16(sb + ATT_QH + so, (const char*)(g_qh + go));
        }
        asm volatile("cp.async.commit_group;");
    }

    auto issue_kv = [&](int kt0, int s) {
        uint32_t sbase = sb + ATT_K + s * ATT_STG;
#pragma unroll
        for (int i = 0; i < 4; i++) {
            int row = (i * 128 + tid) >> 3;
            int c16 = tid & 7;
            uint32_t so = (uint32_t)(row * 128 + c16 * 16) ^ (uint32_t)((row & 7) << 4);
            size_t go = (btok + kt0 + row) * Cz + hoff + c16 * 8;
            CPASYNC16(sbase + so,        (const char*)(g_kh + go));
            CPASYNC16(sbase + 8192 + so, (const char*)(g_vh + go));
        }
        asm volatile("cp.async.commit_group;");
    };

    int lo = qt0 - W; if (lo < 0) lo = 0;
    const int kt_begin = lo & ~63;
    const int nt = ((qt0 - kt_begin) >> 6) + 1;

    issue_kv(kt_begin, 0);

    const int arow = wid * 16 + (lane & 15);
    const uint32_t aswzQ = (uint32_t)((arow & 7) << 4);
    const uint32_t acol_hi = (uint32_t)((lane >> 4) << 4);

    const int r0 = qt0 + wid * 16 + (lane >> 2);
    const int r1 = r0 + 8;
    const int cbase = (lane & 3) * 2;

    float m0 = -1e30f, m1 = -1e30f, l0 = 0.f, l1 = 0.f;
    float o[8][4];
#pragma unroll
    for (int j = 0; j < 8; j++)
#pragma unroll
        for (int q = 0; q < 4; q++) o[j][q] = 0.f;

#pragma unroll 1
    for (int it = 0; it < nt; ++it) {
        const int kt0 = kt_begin + it * 64;
        if (it + 1 < nt) {
            issue_kv(kt0 + 64, (it + 1) & 1);
            asm volatile("cp.async.wait_group 1;");
        } else {
            asm volatile("cp.async.wait_group 0;");
        }
        __syncthreads();

        const uint32_t kvb = sb + ATT_K + (it & 1) * ATT_STG;

        // ---- S = Q K^T (log2 domain)
        float sa[8][4];
#pragma unroll
        for (int j = 0; j < 8; j++)
#pragma unroll
            for (int q = 0; q < 4; q++) sa[j][q] = 0.f;

#pragma unroll
        for (int kk = 0; kk < 4; ++kk) {
            uint32_t ah[4];
            {
                uint32_t bc = ((uint32_t)(kk * 32) + acol_hi) ^ aswzQ;
                uint32_t ra = sb + ATT_QH + (uint32_t)(arow * 128) + bc;
                LDSM4(ah, ra);
            }
            uint32_t kh[4][4];
            {
                const int grp = lane >> 3;
                const int krow_off = (grp >> 1) * 8 + (lane & 7);
                const uint32_t bc_off = (uint32_t)(kk * 32 + (grp & 1) * 16);
#pragma unroll
                for (int p = 0; p < 4; p++) {
                    int krow = p * 16 + krow_off;
                    uint32_t so = (uint32_t)(krow * 128) + (bc_off ^ ((uint32_t)(krow & 7) << 4));
                    LDSM4(kh[p], kvb + so);
                }
            }
#pragma unroll
            for (int p = 0; p < 4; p++) {
                MMAH(sa[2 * p],     ah, kh[p][0], kh[p][1]);
                MMAH(sa[2 * p + 1], ah, kh[p][2], kh[p][3]);
            }
        }

        // ---- online softmax (base-2); interior tiles skip masking
        const bool full = (kt0 + 63 <= qt0) && (qt0 + 63 - kt0 <= W);
        float rm0 = -1e30f, rm1 = -1e30f;
        if (full) {
#pragma unroll
            for (int j = 0; j < 8; j++) {
                rm0 = fmaxf(rm0, fmaxf(sa[j][0], sa[j][1]));
                rm1 = fmaxf(rm1, fmaxf(sa[j][2], sa[j][3]));
            }
        } else {
#pragma unroll
            for (int j = 0; j < 8; j++) {
                const int c0 = kt0 + j * 8 + cbase;
                const int c1 = c0 + 1;
                bool ok00 = (c0 <= r0) && (r0 - c0 <= W);
                bool ok01 = (c1 <= r0) && (r0 - c1 <= W);
                bool ok10 = (c0 <= r1) && (r1 - c0 <= W);
                bool ok11 = (c1 <= r1) && (r1 - c1 <= W);
                sa[j][0] = ok00 ? sa[j][0] : -1e30f;
                sa[j][1] = ok01 ? sa[j][1] : -1e30f;
                sa[j][2] = ok10 ? sa[j][2] : -1e30f;
                sa[j][3] = ok11 ? sa[j][3] : -1e30f;
                rm0 = fmaxf(rm0, fmaxf(sa[j][0], sa[j][1]));
                rm1 = fmaxf(rm1, fmaxf(sa[j][2], sa[j][3]));
            }
        }
#pragma unroll
        for (int off = 1; off <= 2; off <<= 1) {
            rm0 = fmaxf(rm0, __shfl_xor_sync(0xFFFFFFFFu, rm0, off));
            rm1 = fmaxf(rm1, __shfl_xor_sync(0xFFFFFFFFu, rm1, off));
        }
        const float mn0 = fmaxf(m0, rm0);
        const float mn1 = fmaxf(m1, rm1);
        const float corr0 = exp2a(m0 - mn0);
        const float corr1 = exp2a(m1 - mn1);
        m0 = mn0; m1 = mn1;

        float rs0 = 0.f, rs1 = 0.f;
        uint32_t aph[4][4];
        if (full) {
#pragma unroll
            for (int p = 0; p < 4; p++) {
#pragma unroll
                for (int jl = 0; jl < 2; jl++) {
                    const int j = 2 * p + jl;
                    float p0 = exp2a(sa[j][0] - mn0);
                    float p1 = exp2a(sa[j][1] - mn0);
                    float p2 = exp2a(sa[j][2] - mn1);
                    float p3 = exp2a(sa[j][3] - mn1);
                    rs0 += p0 + p1;
                    rs1 += p2 + p3;
                    aph[p][2 * jl + 0] = packh2(p0, p1);
                    aph[p][2 * jl + 1] = packh2(p2, p3);
                }
            }
        } else {
#pragma unroll
            for (int p = 0; p < 4; p++) {
#pragma unroll
                for (int jl = 0; jl < 2; jl++) {
                    const int j = 2 * p + jl;
                    float p0 = (sa[j][0] > -1e29f) ? exp2a(sa[j][0] - mn0) : 0.f;
                    float p1 = (sa[j][1] > -1e29f) ? exp2a(sa[j][1] - mn0) : 0.f;
                    float p2 = (sa[j][2] > -1e29f) ? exp2a(sa[j][2] - mn1) : 0.f;
                    float p3 = (sa[j][3] > -1e29f) ? exp2a(sa[j][3] - mn1) : 0.f;
                    rs0 += p0 + p1;
                    rs1 += p2 + p3;
                    aph[p][2 * jl + 0] = packh2(p0, p1);
                    aph[p][2 * jl + 1] = packh2(p2, p3);
                }
            }
        }
#pragma unroll
        for (int off = 1; off <= 2; off <<= 1) {
            rs0 += __shfl_xor_sync(0xFFFFFFFFu, rs0, off);
            rs1 += __shfl_xor_sync(0xFFFFFFFFu, rs1, off);
        }
        l0 = l0 * corr0 + rs0;
        l1 = l1 * corr1 + rs1;

#pragma unroll
        for (int j = 0; j < 8; j++) {
            o[j][0] *= corr0; o[j][1] *= corr0;
            o[j][2] *= corr1; o[j][3] *= corr1;
        }

        // ---- O += P V
        const uint32_t vbase = kvb + 8192;
        {
            const int vrow_off = lane & 15;
            const uint32_t vcol_hi = (uint32_t)((lane >> 4) << 4);
#pragma unroll
            for (int kk = 0; kk < 4; ++kk) {
                uint32_t vh[4][4];
#pragma unroll
                for (int t = 0; t < 4; t++) {
                    int vrow = kk * 16 + vrow_off;
                    uint32_t bc = ((uint32_t)(t * 32) + vcol_hi) ^ ((uint32_t)(vrow & 7) << 4);
                    LDSM4T(vh[t], vbase + (uint32_t)(vrow * 128) + bc);
                }
#pragma unroll
                for (int t = 0; t < 4; t++) {
                    MMAH(o[2 * t],     aph[kk], vh[t][0], vh[t][1]);
                    MMAH(o[2 * t + 1], aph[kk], vh[t][2], vh[t][3]);
                }
            }
        }
        __syncthreads();
    }

    // epilogue: normalize, write fp16 y
    const float i0 = 1.0f / l0;
    const float i1 = 1.0f / l1;
#pragma unroll
    for (int j = 0; j < 8; j++) {
        size_t col = hoff + j * 8 + cbase;
        size_t idx0 = (btok + r0) * Cz + col;
        size_t idx1 = (btok + r1) * Cz + col;
        *(__half2*)(g_yh + idx0) = __floats2half2_rn(o[j][0] * i0, o[j][1] * i0);
        *(__half2*)(g_yh + idx1) = __floats2half2_rn(o[j][2] * i1, o[j][3] * i1);
    }
}

// ---------------------------------------------------------------------------
extern "C" void kernel_launch(void* const* d_in, const int* in_sizes, int n_in,
                              void* d_out, int out_size)
{
    const float* x     = (const float*)d_in[0];
    const float* ve    = (const float*)d_in[1];
    const float* cosb  = (const float*)d_in[2];
    const float* sinb  = (const float*)d_in[3];
    const float* Wq    = (const float*)d_in[4];
    const float* Wk    = (const float*)d_in[5];
    const float* Wv    = (const float*)d_in[6];
    const float* Wproj = (const float*)d_in[7];
    const float* Wg    = (const float*)d_in[8];
    const int*   win   = (const int*)d_in[9];
    float* out = (float*)d_out;

    __half *qkvh, *xhi, *veh, *whi, *yh;
    cudaGetSymbolAddress((void**)&qkvh, g_qkvh);
    cudaGetSymbolAddress((void**)&xhi, g_xhi);
    cudaGetSymbolAddress((void**)&veh, g_veh);
    cudaGetSymbolAddress((void**)&whi, g_whi);
    cudaGetSymbolAddress((void**)&yh, g_yh);

    const int WW = Cz * Cz;
    const int n4x = TOKz * Cz / 4;
    const int n4w = WW / 4;
    const int n4tot = 2 * n4x + 4 * n4w;

    cvt_all<<<(n4tot + 255) / 256, 256>>>((const float4*)x, (const float4*)ve,
                                          (const float4*)Wq, (const float4*)Wk,
                                          (const float4*)Wv, (const float4*)Wproj,
                                          xhi, veh, whi, n4x, n4w);

    cudaFuncSetAttribute((const void*)gemm_mma<1>,
                         cudaFuncAttributeMaxDynamicSharedMemorySize, GSMEM);
    cudaFuncSetAttribute((const void*)gemm_mma<0>,
                         cudaFuncAttributeMaxDynamicSharedMemorySize, GSMEM);

    // fused QKV GEMM (fp16 out): B = [Wq;Wk;Wv], N = 2304
    gemm_mma<1><<<dim3(QKVN / 128, TOKz / 128), 256, GSMEM>>>(xhi, whi, qkvh, QKVN);

    rope_rms_gate_kernel<<<TOKz, 384>>>(x, cosb, sinb, Wg);

    cudaFuncSetAttribute(attn_mma, cudaFuncAttributeMaxDynamicSharedMemorySize, ATT_SMEM);
    attn_mma<<<dim3(Tz / 64, NHz, Bz), 128, ATT_SMEM>>>(win);

    // projection GEMM (fp32 out): A = y, B = Wproj
    gemm_mma<0><<<dim3(Cz / 128, TOKz / 128), 256, GSMEM>>>(yh, whi + 3 * WW, out, Cz);
}

// round 14
// speedup vs baseline: 1.0817x; 1.0180x over previous
#include <cuda_runtime.h>
#include <cuda_fp16.h>
#include <math.h>
#include <stdint.h>

// Problem constants
#define Bz 4
#define Tz 2048
#define Cz 768
#define NHz 12
#define HDz 64
#define TOKz (Bz * Tz)   // 8192
#define QKVN 2304        // fused q|k|v output width

// fp16 intermediate: fused qkv GEMM output
__device__ __half g_qkvh[TOKz * QKVN];

// fp16 operands
__device__ __half g_xhi[TOKz * Cz];
__device__ __half g_veh[TOKz * Cz];
__device__ __half g_whi[4 * Cz * Cz];   // [Wq;Wk;Wv;Wproj]

// attention operands (q pre-scaled by 1.2*0.125*log2(e))
__device__ __half g_qh[TOKz * Cz];
__device__ __half g_kh[TOKz * Cz];
__device__ __half g_vh[TOKz * Cz];

// attention output (A operand of proj GEMM)
__device__ __half g_yh[TOKz * Cz];

// ---------------------------------------------------------------------------
// Helpers
// ---------------------------------------------------------------------------
__device__ __forceinline__ uint32_t smem_u32(const void* p) {
    uint32_t a;
    asm("{ .reg .u64 t; cvta.to.shared.u64 t, %1; cvt.u32.u64 %0, t; }"
        : "=r"(a) : "l"(p));
    return a;
}

__device__ __forceinline__ float exp2a(float x) {
    float y;
    asm("ex2.approx.f32 %0, %1;" : "=f"(y) : "f"(x));
    return y;
}

#define LDSM4(r, addr)                                                        \
    asm volatile("ldmatrix.sync.aligned.m8n8.x4.shared.b16 {%0,%1,%2,%3}, [%4];" \
                 : "=r"((r)[0]), "=r"((r)[1]), "=r"((r)[2]), "=r"((r)[3])     \
                 : "r"(addr))

#define LDSM4T(r, addr)                                                       \
    asm volatile("ldmatrix.sync.aligned.m8n8.x4.trans.shared.b16 {%0,%1,%2,%3}, [%4];" \
                 : "=r"((r)[0]), "=r"((r)[1]), "=r"((r)[2]), "=r"((r)[3])     \
                 : "r"(addr))

#define LDSM2(r, addr)                                                        \
    asm volatile("ldmatrix.sync.aligned.m8n8.x2.shared.b16 {%0,%1}, [%2];"    \
                 : "=r"((r)[0]), "=r"((r)[1]) : "r"(addr))

#define MMAH(c, a, b0, b1)                                                    \
    asm volatile("mma.sync.aligned.m16n8k16.row.col.f32.f16.f16.f32 "        \
                 "{%0,%1,%2,%3}, {%4,%5,%6,%7}, {%8,%9}, {%0,%1,%2,%3};"     \
                 : "+f"((c)[0]), "+f"((c)[1]), "+f"((c)[2]), "+f"((c)[3])    \
                 : "r"((a)[0]), "r"((a)[1]), "r"((a)[2]), "r"((a)[3]),       \
                   "r"(b0), "r"(b1))

#define CPASYNC16(s, g)                                                       \
    asm volatile("cp.async.ca.shared.global [%0], [%1], 16;" :: "r"(s), "l"(g))

__device__ __forceinline__ uint32_t packh2(float a, float b) {
    __half2 t = __floats2half2_rn(a, b);
    return *(uint32_t*)&t;
}

// ---------------------------------------------------------------------------
// fp16 HMMA GEMM (NT): C[M x N] = A * B^T, K=768, hi-only.
// Block 128x128, 256 thr (8 warps 2m x 4n, warp tile 64x32), occ 2.
// HALFOUT: write C as fp16 (else fp32).
// ---------------------------------------------------------------------------
#define GK 768
#define NCH 12
#define ARR 16384                 // one 128x64 fp16 array (swizzled)
#define STG2 (2 * ARR)            // A, B = 32 KB
#define GSMEM (2 * STG2)          // 64 KB

template <int HALFOUT>
__global__ __launch_bounds__(256, 2) void gemm_mma(
    const __half* __restrict__ Ahi,
    const __half* __restrict__ Bh, void* __restrict__ Cout, int ldc)
{
    extern __shared__ __align__(1024) char dsm[];
    const uint32_t sb = smem_u32(dsm);
    const int tid = threadIdx.x;
    const int wid = tid >> 5, lane = tid & 31;
    const int bm = blockIdx.y << 7;
    const int bn = blockIdx.x << 7;
    const int warp_m = wid >> 2;
    const int warp_n = wid & 3;

    const __half* gA0 = Ahi + (size_t)bm * GK;
    const __half* gB  = Bh  + (size_t)bn * GK;

    const int lrow = tid >> 3;
    const int lc16 = tid & 7;

    float acc[4][4][4];
#pragma unroll
    for (int i = 0; i < 4; i++)
#pragma unroll
        for (int j = 0; j < 4; j++)
#pragma unroll
            for (int k = 0; k < 4; k++) acc[i][j][k] = 0.f;

    auto issue = [&](int c, int s) {
        uint32_t sbase = sb + s * STG2;
#pragma unroll
        for (int i = 0; i < 4; i++) {
            int row = lrow + i * 32;
            uint32_t so = (uint32_t)(row * 128 + lc16 * 16) ^ (uint32_t)((row & 7) << 4);
            size_t go = (size_t)row * GK + c * 64 + lc16 * 8;
            CPASYNC16(sbase + so,       (const char*)(gA0 + go));
            CPASYNC16(sbase + ARR + so, (const char*)(gB + go));
        }
        asm volatile("cp.async.commit_group;");
    };

    issue(0, 0);

    const uint32_t aswz = (uint32_t)((lane & 7) << 4);
    const int arow = warp_m * 64 + (lane & 15);
    const int brow = warp_n * 32 + (lane & 7);
    const uint32_t akhi = (uint32_t)((lane >> 4) << 4);
    const uint32_t bkhi = (uint32_t)(((lane >> 3) & 1) << 4);

#pragma unroll 1
    for (int c = 0; c < NCH; ++c) {
        if (c + 1 < NCH) {
            issue(c + 1, (c + 1) & 1);
            asm volatile("cp.async.wait_group 1;");
        } else {
            asm volatile("cp.async.wait_group 0;");
        }
        __syncthreads();

        const uint32_t sbase = sb + (c & 1) * STG2;
#pragma unroll
        for (int ks = 0; ks < 4; ++ks) {
            uint32_t ah[4][4], bh[4][2];
            const uint32_t ak = ((uint32_t)(ks * 32) + akhi) ^ aswz;
            const uint32_t bk = ((uint32_t)(ks * 32) + bkhi) ^ aswz;
#pragma unroll
            for (int mt = 0; mt < 4; mt++) {
                uint32_t ra = sbase + (uint32_t)((arow + mt * 16) * 128) + ak;
                LDSM4(ah[mt], ra);
            }
#pragma unroll
            for (int nt = 0; nt < 4; nt++) {
                uint32_t rb = sbase + ARR + (uint32_t)((brow + nt * 8) * 128) + bk;
                LDSM2(bh[nt], rb);
            }
#pragma unroll
            for (int mt = 0; mt < 4; mt++)
#pragma unroll
                for (int nt = 0; nt < 4; nt++)
                    MMAH(acc[mt][nt], ah[mt], bh[nt][0], bh[nt][1]);
        }
        __syncthreads();
    }

    const int crow = bm + warp_m * 64 + (lane >> 2);
    const int ccol = bn + warp_n * 32 + (lane & 3) * 2;
    if (HALFOUT) {
        __half* C = (__half*)Cout;
#pragma unroll
        for (int mt = 0; mt < 4; mt++)
#pragma unroll
            for (int nt = 0; nt < 4; nt++) {
                __half* p0 = C + (size_t)(crow + mt * 16) * ldc + ccol + nt * 8;
                __half* p1 = p0 + 8 * ldc;
                *(__half2*)p0 = __floats2half2_rn(acc[mt][nt][0], acc[mt][nt][1]);
                *(__half2*)p1 = __floats2half2_rn(acc[mt][nt][2], acc[mt][nt][3]);
            }
    } else {
        float* C = (float*)Cout;
#pragma unroll
        for (int mt = 0; mt < 4; mt++)
#pragma unroll
            for (int nt = 0; nt < 4; nt++) {
                float* p0 = C + (size_t)(crow + mt * 16) * ldc + ccol + nt * 8;
                float* p1 = p0 + 8 * ldc;
                *(float2*)p0 = make_float2(acc[mt][nt][0], acc[mt][nt][1]);
                *(float2*)p1 = make_float2(acc[mt][nt][2], acc[mt][nt][3]);
            }
    }
}

// ---------------------------------------------------------------------------
// Fused fp32 -> fp16 convert: x, ve, then 4 weight matrices
// ---------------------------------------------------------------------------
__global__ void cvt_all(const float4* __restrict__ x, const float4* __restrict__ ve,
                        const float4* __restrict__ w0, const float4* __restrict__ w1,
                        const float4* __restrict__ w2, const float4* __restrict__ w3,
                        __half* __restrict__ xhi, __half* __restrict__ veh,
                        __half* __restrict__ whi, int n4x, int n4w)
{
    int i = blockIdx.x * 256 + threadIdx.x;
    const float4* src;
    __half* dst;
    int r;
    if (i < n4x) {
        src = x; dst = xhi; r = i;
    } else if (i < 2 * n4x) {
        src = ve; dst = veh; r = i - n4x;
    } else {
        int j = i - 2 * n4x;
        int m = j / n4w;
        if (m >= 4) return;
        r = j - m * n4w;
        src = (m == 0) ? w0 : (m == 1) ? w1 : (m == 2) ? w2 : w3;
        dst = whi + (size_t)m * (Cz * Cz);
    }
    float4 v = src[r];
    ((__half2*)dst)[2 * r]     = __half2(__float2half(v.x), __float2half(v.y));
    ((__half2*)dst)[2 * r + 1] = __half2(__float2half(v.z), __float2half(v.w));
}

// ---------------------------------------------------------------------------
// RoPE + RMSNorm + gated ve add; q scale = 1.2 * 0.125 * log2(e)
// ---------------------------------------------------------------------------
#define QSCALE 0.21640425613334451f   // 0.15 * log2(e)

__global__ __launch_bounds__(384) void rope_rms_gate_kernel(
    const float* __restrict__ x,
    const float* __restrict__ cosb, const float* __restrict__ sinb,
    const float* __restrict__ Wg)
{
    const int tok = blockIdx.x;
    const int t = tok & (Tz - 1);
    const int h = threadIdx.x >> 5;
    const int lane = threadIdx.x & 31;
    const size_t qkvbase = (size_t)tok * QKVN + h * HDz;
    const size_t base = (size_t)tok * Cz + h * HDz;

    const float cv = cosb[t * 32 + lane];
    const float sv = sinb[t * 32 + lane];

    {   // q: rope + rms (* QSCALE)
        float x1 = __half2float(g_qkvh[qkvbase + lane]);
        float x2 = __half2float(g_qkvh[qkvbase + 32 + lane]);
        float r1 = x1 * cv - x2 * sv;
        float r2 = x1 * sv + x2 * cv;
        float ss = r1 * r1 + r2 * r2;
#pragma unroll
        for (int o = 16; o > 0; o >>= 1) ss += __shfl_xor_sync(0xFFFFFFFFu, ss, o);
        float inv = rsqrtf(ss * (1.0f / 64.0f) + 1e-6f) * QSCALE;
        g_qh[base + lane] = __float2half(r1 * inv);
        g_qh[base + 32 + lane] = __float2half(r2 * inv);
    }
    {   // k: rope + rms (* 1.2)
        float x1 = __half2float(g_qkvh[qkvbase + Cz + lane]);
        float x2 = __half2float(g_qkvh[qkvbase + Cz + 32 + lane]);
        float r1 = x1 * cv - x2 * sv;
        float r2 = x1 * sv + x2 * cv;
        float ss = r1 * r1 + r2 * r2;
#pragma unroll
        for (int o = 16; o > 0; o >>= 1) ss += __shfl_xor_sync(0xFFFFFFFFu, ss, o);
        float inv = rsqrtf(ss * (1.0f / 64.0f) + 1e-6f) * 1.2f;
        g_kh[base + lane] = __float2half(r1 * inv);
        g_kh[base + 32 + lane] = __float2half(r2 * inv);
    }
    {   // v: gated ve add
        float p = (lane < 12) ? x[(size_t)tok * Cz + lane] * Wg[h * 12 + lane] : 0.f;
#pragma unroll
        for (int o = 16; o > 0; o >>= 1) p += __shfl_xor_sync(0xFFFFFFFFu, p, o);
        float gate = 3.0f / (1.0f + __expf(-p));
        float v1 = __half2float(g_qkvh[qkvbase + 2 * Cz + lane])
                 + gate * __half2float(g_veh[base + lane]);
        float v2 = __half2float(g_qkvh[qkvbase + 2 * Cz + 32 + lane])
                 + gate * __half2float(g_veh[base + 32 + lane]);
        g_vh[base + lane] = __float2half(v1);
        g_vh[base + 32 + lane] = __float2half(v2);
    }
}

// ---------------------------------------------------------------------------
// MMA flash attention, 64-query CTA (4 warps, occ 4), sliding window.
// S in log2 domain (scale folded into q); exp2 softmax.
// Single barrier per iteration: [wait; barrier; issue(it+1); compute(it)].
// smem: Q 8K | 2 stages of (K 8K + V 8K) = 40 KB.
// ---------------------------------------------------------------------------
#define ATT_QH 0
#define ATT_K  8192
#define ATT_STG 16384
#define ATT_SMEM (8192 + 2 * ATT_STG)   // 40960

__global__ __launch_bounds__(128, 4) void attn_mma(const int* __restrict__ winp)
{
    extern __shared__ __align__(1024) char dsm[];
    const uint32_t sb = smem_u32(dsm);
    const int tid = threadIdx.x;
    const int wid = tid >> 5, lane = tid & 31;
    const int qt0 = (gridDim.x - 1 - blockIdx.x) * 64;   // longest-first
    const int h = blockIdx.y;
    const int b = blockIdx.z;
    const int W = *winp;

    const size_t hoff = (size_t)h * HDz;
    const size_t btok = (size_t)b * Tz;

    // ---- load Q (group 0)
    {
#pragma unroll
        for (int i = 0; i < 4; i++) {
            int row = (i * 128 + tid) >> 3;
            int c16 = tid & 7;
            uint32_t so = (uint32_t)(row * 128 + c16 * 16) ^ (uint32_t)((row & 7) << 4);
            size_t go = (btok + qt0 + row) * Cz + hoff + c16 * 8;
            CPASYNC16(sb + ATT_QH + so, (const char*)(g_qh + go));
        }
        asm volatile("cp.async.commit_group;");
    }

    auto issue_kv = [&](int kt0, int s) {
        uint32_t sbase = sb + ATT_K + s * ATT_STG;
#pragma unroll
        for (int i = 0; i < 4; i++) {
            int row = (i * 128 + tid) >> 3;
            int c16 = tid & 7;
            uint32_t so = (uint32_t)(row * 128 + c16 * 16) ^ (uint32_t)((row & 7) << 4);
            size_t go = (btok + kt0 + row) * Cz + hoff + c16 * 8;
            CPASYNC16(sbase + so,        (const char*)(g_kh + go));
            CPASYNC16(sbase + 8192 + so, (const char*)(g_vh + go));
        }
        asm volatile("cp.async.commit_group;");
    };

    int lo = qt0 - W; if (lo < 0) lo = 0;
    const int kt_begin = lo & ~63;
    const int nt = ((qt0 - kt_begin) >> 6) + 1;

    issue_kv(kt_begin, 0);

    const int arow = wid * 16 + (lane & 15);
    const uint32_t aswzQ = (uint32_t)((arow & 7) << 4);
    const uint32_t acol_hi = (uint32_t)((lane >> 4) << 4);

    const int r0 = qt0 + wid * 16 + (lane >> 2);
    const int r1 = r0 + 8;
    const int cbase = (lane & 3) * 2;

    float m0 = -1e30f, m1 = -1e30f, l0 = 0.f, l1 = 0.f;
    float o[8][4];
#pragma unroll
    for (int j = 0; j < 8; j++)
#pragma unroll
        for (int q = 0; q < 4; q++) o[j][q] = 0.f;

#pragma unroll 1
    for (int it = 0; it < nt; ++it) {
        const int kt0 = kt_begin + it * 64;

        // wait for tile `it` (and Q on it==0), then hand buffers over
        asm volatile("cp.async.wait_group 0;");
        __syncthreads();
        // prefetch next tile into the other stage (overlaps compute below);
        // safe: barrier above guarantees stage (it+1)&1 is no longer read.
        if (it + 1 < nt) issue_kv(kt0 + 64, (it + 1) & 1);

        const uint32_t kvb = sb + ATT_K + (it & 1) * ATT_STG;

        // ---- S = Q K^T (log2 domain)
        float sa[8][4];
#pragma unroll
        for (int j = 0; j < 8; j++)
#pragma unroll
            for (int q = 0; q < 4; q++) sa[j][q] = 0.f;

#pragma unroll
        for (int kk = 0; kk < 4; ++kk) {
            uint32_t ah[4];
            {
                uint32_t bc = ((uint32_t)(kk * 32) + acol_hi) ^ aswzQ;
                uint32_t ra = sb + ATT_QH + (uint32_t)(arow * 128) + bc;
                LDSM4(ah, ra);
            }
            uint32_t kh[4][4];
            {
                const int grp = lane >> 3;
                const int krow_off = (grp >> 1) * 8 + (lane & 7);
                const uint32_t bc_off = (uint32_t)(kk * 32 + (grp & 1) * 16);
#pragma unroll
                for (int p = 0; p < 4; p++) {
                    int krow = p * 16 + krow_off;
                    uint32_t so = (uint32_t)(krow * 128) + (bc_off ^ ((uint32_t)(krow & 7) << 4));
                    LDSM4(kh[p], kvb + so);
                }
            }
#pragma unroll
            for (int p = 0; p < 4; p++) {
                MMAH(sa[2 * p],     ah, kh[p][0], kh[p][1]);
                MMAH(sa[2 * p + 1], ah, kh[p][2], kh[p][3]);
            }
        }

        // ---- online softmax (base-2); interior tiles skip masking
        const bool full = (kt0 + 63 <= qt0) && (qt0 + 63 - kt0 <= W);
        float rm0 = -1e30f, rm1 = -1e30f;
        if (full) {
#pragma unroll
            for (int j = 0; j < 8; j++) {
                rm0 = fmaxf(rm0, fmaxf(sa[j][0], sa[j][1]));
                rm1 = fmaxf(rm1, fmaxf(sa[j][2], sa[j][3]));
            }
        } else {
#pragma unroll
            for (int j = 0; j < 8; j++) {
                const int c0 = kt0 + j * 8 + cbase;
                const int c1 = c0 + 1;
                bool ok00 = (c0 <= r0) && (r0 - c0 <= W);
                bool ok01 = (c1 <= r0) && (r0 - c1 <= W);
                bool ok10 = (c0 <= r1) && (r1 - c0 <= W);
                bool ok11 = (c1 <= r1) && (r1 - c1 <= W);
                sa[j][0] = ok00 ? sa[j][0] : -1e30f;
                sa[j][1] = ok01 ? sa[j][1] : -1e30f;
                sa[j][2] = ok10 ? sa[j][2] : -1e30f;
                sa[j][3] = ok11 ? sa[j][3] : -1e30f;
                rm0 = fmaxf(rm0, fmaxf(sa[j][0], sa[j][1]));
                rm1 = fmaxf(rm1, fmaxf(sa[j][2], sa[j][3]));
            }
        }
#pragma unroll
        for (int off = 1; off <= 2; off <<= 1) {
            rm0 = fmaxf(rm0, __shfl_xor_sync(0xFFFFFFFFu, rm0, off));
            rm1 = fmaxf(rm1, __shfl_xor_sync(0xFFFFFFFFu, rm1, off));
        }
        const float mn0 = fmaxf(m0, rm0);
        const float mn1 = fmaxf(m1, rm1);
        const float corr0 = exp2a(m0 - mn0);
        const float corr1 = exp2a(m1 - mn1);
        m0 = mn0; m1 = mn1;

        // exp2 of masked (-1e30) entries flushes to exactly 0 — no predicate needed
        float rs0 = 0.f, rs1 = 0.f;
        uint32_t aph[4][4];
#pragma unroll
        for (int p = 0; p < 4; p++) {
#pragma unroll
            for (int jl = 0; jl < 2; jl++) {
                const int j = 2 * p + jl;
                float p0 = exp2a(sa[j][0] - mn0);
                float p1 = exp2a(sa[j][1] - mn0);
                float p2 = exp2a(sa[j][2] - mn1);
                float p3 = exp2a(sa[j][3] - mn1);
                rs0 += p0 + p1;
                rs1 += p2 + p3;
                aph[p][2 * jl + 0] = packh2(p0, p1);
                aph[p][2 * jl + 1] = packh2(p2, p3);
            }
        }
#pragma unroll
        for (int off = 1; off <= 2; off <<= 1) {
            rs0 += __shfl_xor_sync(0xFFFFFFFFu, rs0, off);
            rs1 += __shfl_xor_sync(0xFFFFFFFFu, rs1, off);
        }
        l0 = l0 * corr0 + rs0;
        l1 = l1 * corr1 + rs1;

#pragma unroll
        for (int j = 0; j < 8; j++) {
            o[j][0] *= corr0; o[j][1] *= corr0;
            o[j][2] *= corr1; o[j][3] *= corr1;
        }

        // ---- O += P V
        const uint32_t vbase = kvb + 8192;
        {
            const int vrow_off = lane & 15;
            const uint32_t vcol_hi = (uint32_t)((lane >> 4) << 4);
#pragma unroll
            for (int kk = 0; kk < 4; ++kk) {
                uint32_t vh[4][4];
#pragma unroll
                for (int t = 0; t < 4; t++) {
                    int vrow = kk * 16 + vrow_off;
                    uint32_t bc = ((uint32_t)(t * 32) + vcol_hi) ^ ((uint32_t)(vrow & 7) << 4);
                    LDSM4T(vh[t], vbase + (uint32_t)(vrow * 128) + bc);
                }
#pragma unroll
                for (int t = 0; t < 4; t++) {
                    MMAH(o[2 * t],     aph[kk], vh[t][0], vh[t][1]);
                    MMAH(o[2 * t + 1], aph[kk], vh[t][2], vh[t][3]);
                }
            }
        }
        // no end-of-loop barrier: top barrier of next iter protects stage reuse
    }

    // epilogue: normalize, write fp16 y
    const float i0 = 1.0f / l0;
    const float i1 = 1.0f / l1;
#pragma unroll
    for (int j = 0; j < 8; j++) {
        size_t col = hoff + j * 8 + cbase;
        size_t idx0 = (btok + r0) * Cz + col;
        size_t idx1 = (btok + r1) * Cz + col;
        *(__half2*)(g_yh + idx0) = __floats2half2_rn(o[j][0] * i0, o[j][1] * i0);
        *(__half2*)(g_yh + idx1) = __floats2half2_rn(o[j][2] * i1, o[j][3] * i1);
    }
}

// ---------------------------------------------------------------------------
extern "C" void kernel_launch(void* const* d_in, const int* in_sizes, int n_in,
                              void* d_out, int out_size)
{
    const float* x     = (const float*)d_in[0];
    const float* ve    = (const float*)d_in[1];
    const float* cosb  = (const float*)d_in[2];
    const float* sinb  = (const float*)d_in[3];
    const float* Wq    = (const float*)d_in[4];
    const float* Wk    = (const float*)d_in[5];
    const float* Wv    = (const float*)d_in[6];
    const float* Wproj = (const float*)d_in[7];
    const float* Wg    = (const float*)d_in[8];
    const int*   win   = (const int*)d_in[9];
    float* out = (float*)d_out;

    __half *qkvh, *xhi, *veh, *whi, *yh;
    cudaGetSymbolAddress((void**)&qkvh, g_qkvh);
    cudaGetSymbolAddress((void**)&xhi, g_xhi);
    cudaGetSymbolAddress((void**)&veh, g_veh);
    cudaGetSymbolAddress((void**)&whi, g_whi);
    cudaGetSymbolAddress((void**)&yh, g_yh);

    const int WW = Cz * Cz;
    const int n4x = TOKz * Cz / 4;
    const int n4w = WW / 4;
    const int n4tot = 2 * n4x + 4 * n4w;

    cvt_all<<<(n4tot + 255) / 256, 256>>>((const float4*)x, (const float4*)ve,
                                          (const float4*)Wq, (const float4*)Wk,
                                          (const float4*)Wv, (const float4*)Wproj,
                                          xhi, veh, whi, n4x, n4w);

    cudaFuncSetAttribute((const void*)gemm_mma<1>,
                         cudaFuncAttributeMaxDynamicSharedMemorySize, GSMEM);
    cudaFuncSetAttribute((const void*)gemm_mma<0>,
                         cudaFuncAttributeMaxDynamicSharedMemorySize, GSMEM);

    // fused QKV GEMM (fp16 out): B = [Wq;Wk;Wv], N = 2304
    gemm_mma<1><<<dim3(QKVN / 128, TOKz / 128), 256, GSMEM>>>(xhi, whi, qkvh, QKVN);

    rope_rms_gate_kernel<<<TOKz, 384>>>(x, cosb, sinb, Wg);

    cudaFuncSetAttribute(attn_mma, cudaFuncAttributeMaxDynamicSharedMemorySize, ATT_SMEM);
    attn_mma<<<dim3(Tz / 64, NHz, Bz), 128, ATT_SMEM>>>(win);

    // projection GEMM (fp32 out): A = y, B = Wproj
    gemm_mma<0><<<dim3(Cz / 128, TOKz / 128), 256, GSMEM>>>(yh, whi + 3 * WW, out, Cz);
}

// round 15
// speedup vs baseline: 1.1335x; 1.0479x over previous
#include <cuda_runtime.h>
#include <cuda_fp16.h>
#include <math.h>
#include <stdint.h>

// Problem constants
#define Bz 4
#define Tz 2048
#define Cz 768
#define NHz 12
#define HDz 64
#define TOKz (Bz * Tz)   // 8192
#define QKVN 2304        // fused q|k|v output width

// fp16 intermediate: fused qkv GEMM output
__device__ __half g_qkvh[TOKz * QKVN];

// fp16 operands
__device__ __half g_xhi[TOKz * Cz];
__device__ __half g_veh[TOKz * Cz];
__device__ __half g_whi[4 * Cz * Cz];   // [Wq;Wk;Wv;Wproj]

// attention operands (q pre-scaled by 1.2*0.125*log2(e))
__device__ __half g_qh[TOKz * Cz];
__device__ __half g_kh[TOKz * Cz];
__device__ __half g_vh[TOKz * Cz];

// attention output (A operand of proj GEMM)
__device__ __half g_yh[TOKz * Cz];

// ---------------------------------------------------------------------------
// Helpers
// ---------------------------------------------------------------------------
__device__ __forceinline__ uint32_t smem_u32(const void* p) {
    uint32_t a;
    asm("{ .reg .u64 t; cvta.to.shared.u64 t, %1; cvt.u32.u64 %0, t; }"
        : "=r"(a) : "l"(p));
    return a;
}

__device__ __forceinline__ float exp2a(float x) {
    float y;
    asm("ex2.approx.f32 %0, %1;" : "=f"(y) : "f"(x));
    return y;
}

#define LDSM4(r, addr)                                                        \
    asm volatile("ldmatrix.sync.aligned.m8n8.x4.shared.b16 {%0,%1,%2,%3}, [%4];" \
                 : "=r"((r)[0]), "=r"((r)[1]), "=r"((r)[2]), "=r"((r)[3])     \
                 : "r"(addr))

#define LDSM4T(r, addr)                                                       \
    asm volatile("ldmatrix.sync.aligned.m8n8.x4.trans.shared.b16 {%0,%1,%2,%3}, [%4];" \
                 : "=r"((r)[0]), "=r"((r)[1]), "=r"((r)[2]), "=r"((r)[3])     \
                 : "r"(addr))

#define LDSM2(r, addr)                                                        \
    asm volatile("ldmatrix.sync.aligned.m8n8.x2.shared.b16 {%0,%1}, [%2];"    \
                 : "=r"((r)[0]), "=r"((r)[1]) : "r"(addr))

#define MMAH(c, a, b0, b1)                                                    \
    asm volatile("mma.sync.aligned.m16n8k16.row.col.f32.f16.f16.f32 "        \
                 "{%0,%1,%2,%3}, {%4,%5,%6,%7}, {%8,%9}, {%0,%1,%2,%3};"     \
                 : "+f"((c)[0]), "+f"((c)[1]), "+f"((c)[2]), "+f"((c)[3])    \
                 : "r"((a)[0]), "r"((a)[1]), "r"((a)[2]), "r"((a)[3]),       \
                   "r"(b0), "r"(b1))

#define CPASYNC16(s, g)                                                       \
    asm volatile("cp.async.ca.shared.global [%0], [%1], 16;" :: "r"(s), "l"(g))

__device__ __forceinline__ uint32_t packh2(float a, float b) {
    __half2 t = __floats2half2_rn(a, b);
    return *(uint32_t*)&t;
}

// ---------------------------------------------------------------------------
// fp16 HMMA GEMM (NT): C[M x N] = A * B^T, K=768, hi-only.
// Block 128x128, 256 thr (8 warps 2m x 4n, warp tile 64x32), occ 2.
// HALFOUT: write C as fp16 (else fp32).
// ---------------------------------------------------------------------------
#define GK 768
#define NCH 12
#define ARR 16384                 // one 128x64 fp16 array (swizzled)
#define STG2 (2 * ARR)            // A, B = 32 KB
#define GSMEM (2 * STG2)          // 64 KB

template <int HALFOUT>
__global__ __launch_bounds__(256, 2) void gemm_mma(
    const __half* __restrict__ Ahi,
    const __half* __restrict__ Bh, void* __restrict__ Cout, int ldc)
{
    extern __shared__ __align__(1024) char dsm[];
    const uint32_t sb = smem_u32(dsm);
    const int tid = threadIdx.x;
    const int wid = tid >> 5, lane = tid & 31;
    const int bm = blockIdx.y << 7;
    const int bn = blockIdx.x << 7;
    const int warp_m = wid >> 2;
    const int warp_n = wid & 3;

    const __half* gA0 = Ahi + (size_t)bm * GK;
    const __half* gB  = Bh  + (size_t)bn * GK;

    const int lrow = tid >> 3;
    const int lc16 = tid & 7;

    float acc[4][4][4];
#pragma unroll
    for (int i = 0; i < 4; i++)
#pragma unroll
        for (int j = 0; j < 4; j++)
#pragma unroll
            for (int k = 0; k < 4; k++) acc[i][j][k] = 0.f;

    auto issue = [&](int c, int s) {
        uint32_t sbase = sb + s * STG2;
#pragma unroll
        for (int i = 0; i < 4; i++) {
            int row = lrow + i * 32;
            uint32_t so = (uint32_t)(row * 128 + lc16 * 16) ^ (uint32_t)((row & 7) << 4);
            size_t go = (size_t)row * GK + c * 64 + lc16 * 8;
            CPASYNC16(sbase + so,       (const char*)(gA0 + go));
            CPASYNC16(sbase + ARR + so, (const char*)(gB + go));
        }
        asm volatile("cp.async.commit_group;");
    };

    issue(0, 0);

    const uint32_t aswz = (uint32_t)((lane & 7) << 4);
    const int arow = warp_m * 64 + (lane & 15);
    const int brow = warp_n * 32 + (lane & 7);
    const uint32_t akhi = (uint32_t)((lane >> 4) << 4);
    const uint32_t bkhi = (uint32_t)(((lane >> 3) & 1) << 4);

#pragma unroll 1
    for (int c = 0; c < NCH; ++c) {
        if (c + 1 < NCH) {
            issue(c + 1, (c + 1) & 1);
            asm volatile("cp.async.wait_group 1;");
        } else {
            asm volatile("cp.async.wait_group 0;");
        }
        __syncthreads();

        const uint32_t sbase = sb + (c & 1) * STG2;
#pragma unroll
        for (int ks = 0; ks < 4; ++ks) {
            uint32_t ah[4][4], bh[4][2];
            const uint32_t ak = ((uint32_t)(ks * 32) + akhi) ^ aswz;
            const uint32_t bk = ((uint32_t)(ks * 32) + bkhi) ^ aswz;
#pragma unroll
            for (int mt = 0; mt < 4; mt++) {
                uint32_t ra = sbase + (uint32_t)((arow + mt * 16) * 128) + ak;
                LDSM4(ah[mt], ra);
            }
#pragma unroll
            for (int nt = 0; nt < 4; nt++) {
                uint32_t rb = sbase + ARR + (uint32_t)((brow + nt * 8) * 128) + bk;
                LDSM2(bh[nt], rb);
            }
#pragma unroll
            for (int mt = 0; mt < 4; mt++)
#pragma unroll
                for (int nt = 0; nt < 4; nt++)
                    MMAH(acc[mt][nt], ah[mt], bh[nt][0], bh[nt][1]);
        }
        __syncthreads();
    }

    const int crow = bm + warp_m * 64 + (lane >> 2);
    const int ccol = bn + warp_n * 32 + (lane & 3) * 2;
    if (HALFOUT) {
        __half* C = (__half*)Cout;
#pragma unroll
        for (int mt = 0; mt < 4; mt++)
#pragma unroll
            for (int nt = 0; nt < 4; nt++) {
                __half* p0 = C + (size_t)(crow + mt * 16) * ldc + ccol + nt * 8;
                __half* p1 = p0 + 8 * ldc;
                *(__half2*)p0 = __floats2half2_rn(acc[mt][nt][0], acc[mt][nt][1]);
                *(__half2*)p1 = __floats2half2_rn(acc[mt][nt][2], acc[mt][nt][3]);
            }
    } else {
        float* C = (float*)Cout;
#pragma unroll
        for (int mt = 0; mt < 4; mt++)
#pragma unroll
            for (int nt = 0; nt < 4; nt++) {
                float* p0 = C + (size_t)(crow + mt * 16) * ldc + ccol + nt * 8;
                float* p1 = p0 + 8 * ldc;
                *(float2*)p0 = make_float2(acc[mt][nt][0], acc[mt][nt][1]);
                *(float2*)p1 = make_float2(acc[mt][nt][2], acc[mt][nt][3]);
            }
    }
}

// ---------------------------------------------------------------------------
// Fused fp32 -> fp16 convert: x, ve, then 4 weight matrices
// ---------------------------------------------------------------------------
__global__ void cvt_all(const float4* __restrict__ x, const float4* __restrict__ ve,
                        const float4* __restrict__ w0, const float4* __restrict__ w1,
                        const float4* __restrict__ w2, const float4* __restrict__ w3,
                        __half* __restrict__ xhi, __half* __restrict__ veh,
                        __half* __restrict__ whi, int n4x, int n4w)
{
    int i = blockIdx.x * 256 + threadIdx.x;
    const float4* src;
    __half* dst;
    int r;
    if (i < n4x) {
        src = x; dst = xhi; r = i;
    } else if (i < 2 * n4x) {
        src = ve; dst = veh; r = i - n4x;
    } else {
        int j = i - 2 * n4x;
        int m = j / n4w;
        if (m >= 4) return;
        r = j - m * n4w;
        src = (m == 0) ? w0 : (m == 1) ? w1 : (m == 2) ? w2 : w3;
        dst = whi + (size_t)m * (Cz * Cz);
    }
    float4 v = src[r];
    ((__half2*)dst)[2 * r]     = __half2(__float2half(v.x), __float2half(v.y));
    ((__half2*)dst)[2 * r + 1] = __half2(__float2half(v.z), __float2half(v.w));
}

// ---------------------------------------------------------------------------
// RoPE + RMSNorm + gated ve add — vectorized (half2/float2 I/O).
// 192 threads = 6 warps; each half-warp (16 lanes) owns one head.
// Lane l handles rope pairs (2l, 2l+1): dims {2l,2l+1} x {+0,+32}.
// q scale = 1.2 * 0.125 * log2(e).
// ---------------------------------------------------------------------------
#define QSCALE 0.21640425613334451f   // 0.15 * log2(e)

__global__ __launch_bounds__(192) void rope_rms_gate_kernel(
    const float* __restrict__ x,
    const float* __restrict__ cosb, const float* __restrict__ sinb,
    const float* __restrict__ Wg)
{
    const int tok = blockIdx.x;
    const int t = tok & (Tz - 1);
    const int warp = threadIdx.x >> 5;
    const int lane = threadIdx.x & 31;
    const int half = lane >> 4;
    const int l = lane & 15;
    const int h = warp * 2 + half;

    const size_t qkvbase = (size_t)tok * QKVN + h * HDz;
    const size_t base = (size_t)tok * Cz + h * HDz;

    const float2 cv = *(const float2*)(cosb + t * 32 + 2 * l);
    const float2 sv = *(const float2*)(sinb + t * 32 + 2 * l);

    {   // q: rope + rms (* QSCALE)
        __half2 a = *(const __half2*)(g_qkvh + qkvbase + 2 * l);
        __half2 b = *(const __half2*)(g_qkvh + qkvbase + 32 + 2 * l);
        float x1a = __half2float(a.x), x1b = __half2float(a.y);
        float x2a = __half2float(b.x), x2b = __half2float(b.y);
        float r1a = x1a * cv.x - x2a * sv.x, r1b = x1b * cv.y - x2b * sv.y;
        float r2a = x1a * sv.x + x2a * cv.x, r2b = x1b * sv.y + x2b * cv.y;
        float ss = r1a * r1a + r1b * r1b + r2a * r2a + r2b * r2b;
#pragma unroll
        for (int o = 8; o > 0; o >>= 1) ss += __shfl_xor_sync(0xFFFFFFFFu, ss, o);
        float inv = rsqrtf(ss * (1.0f / 64.0f) + 1e-6f) * QSCALE;
        *(__half2*)(g_qh + base + 2 * l)      = __floats2half2_rn(r1a * inv, r1b * inv);
        *(__half2*)(g_qh + base + 32 + 2 * l) = __floats2half2_rn(r2a * inv, r2b * inv);
    }
    {   // k: rope + rms (* 1.2)
        __half2 a = *(const __half2*)(g_qkvh + qkvbase + Cz + 2 * l);
        __half2 b = *(const __half2*)(g_qkvh + qkvbase + Cz + 32 + 2 * l);
        float x1a = __half2float(a.x), x1b = __half2float(a.y);
        float x2a = __half2float(b.x), x2b = __half2float(b.y);
        float r1a = x1a * cv.x - x2a * sv.x, r1b = x1b * cv.y - x2b * sv.y;
        float r2a = x1a * sv.x + x2a * cv.x, r2b = x1b * sv.y + x2b * cv.y;
        float ss = r1a * r1a + r1b * r1b + r2a * r2a + r2b * r2b;
#pragma unroll
        for (int o = 8; o > 0; o >>= 1) ss += __shfl_xor_sync(0xFFFFFFFFu, ss, o);
        float inv = rsqrtf(ss * (1.0f / 64.0f) + 1e-6f) * 1.2f;
        *(__half2*)(g_kh + base + 2 * l)      = __floats2half2_rn(r1a * inv, r1b * inv);
        *(__half2*)(g_kh + base + 32 + 2 * l) = __floats2half2_rn(r2a * inv, r2b * inv);
    }
    {   // v: gated ve add
        float p = (l < 12) ? x[(size_t)tok * Cz + l] * Wg[h * 12 + l] : 0.f;
#pragma unroll
        for (int o = 8; o > 0; o >>= 1) p += __shfl_xor_sync(0xFFFFFFFFu, p, o);
        float gate = 3.0f / (1.0f + __expf(-p));
        __half2 va = *(const __half2*)(g_qkvh + qkvbase + 2 * Cz + 2 * l);
        __half2 vb = *(const __half2*)(g_qkvh + qkvbase + 2 * Cz + 32 + 2 * l);
        __half2 ea = *(const __half2*)(g_veh + base + 2 * l);
        __half2 eb = *(const __half2*)(g_veh + base + 32 + 2 * l);
        *(__half2*)(g_vh + base + 2 * l) = __floats2half2_rn(
            __half2float(va.x) + gate * __half2float(ea.x),
            __half2float(va.y) + gate * __half2float(ea.y));
        *(__half2*)(g_vh + base + 32 + 2 * l) = __floats2half2_rn(
            __half2float(vb.x) + gate * __half2float(eb.x),
            __half2float(vb.y) + gate * __half2float(eb.y));
    }
}

// ---------------------------------------------------------------------------
// MMA flash attention, 64-query CTA (4 warps, occ 4), sliding window.
// S in log2 domain; exp2 softmax; Q fragments hoisted into registers.
// Pipeline: [pre: wait+bar+loadQ] then per iter: (wait+bar if it>0),
// issue(it+1), compute(it).
// smem: Q 8K | 2 stages of (K 8K + V 8K) = 40 KB.
// ---------------------------------------------------------------------------
#define ATT_QH 0
#define ATT_K  8192
#define ATT_STG 16384
#define ATT_SMEM (8192 + 2 * ATT_STG)   // 40960

__global__ __launch_bounds__(128, 4) void attn_mma(const int* __restrict__ winp)
{
    extern __shared__ __align__(1024) char dsm[];
    const uint32_t sb = smem_u32(dsm);
    const int tid = threadIdx.x;
    const int wid = tid >> 5, lane = tid & 31;
    const int qt0 = (gridDim.x - 1 - blockIdx.x) * 64;   // longest-first
    const int h = blockIdx.y;
    const int b = blockIdx.z;
    const int W = *winp;

    const size_t hoff = (size_t)h * HDz;
    const size_t btok = (size_t)b * Tz;

    // ---- load Q
    {
#pragma unroll
        for (int i = 0; i < 4; i++) {
            int row = (i * 128 + tid) >> 3;
            int c16 = tid & 7;
            uint32_t so = (uint32_t)(row * 128 + c16 * 16) ^ (uint32_t)((row & 7) << 4);
            size_t go = (btok + qt0 + row) * Cz + hoff + c16 * 8;
            CPASYNC16(sb + ATT_QH + so, (const char*)(g_qh + go));
        }
        asm volatile("cp.async.commit_group;");
    }

    auto issue_kv = [&](int kt0, int s) {
        uint32_t sbase = sb + ATT_K + s * ATT_STG;
#pragma unroll
        for (int i = 0; i < 4; i++) {
            int row = (i * 128 + tid) >> 3;
            int c16 = tid & 7;
            uint32_t so = (uint32_t)(row * 128 + c16 * 16) ^ (uint32_t)((row & 7) << 4);
            size_t go = (btok + kt0 + row) * Cz + hoff + c16 * 8;
            CPASYNC16(sbase + so,        (const char*)(g_kh + go));
            CPASYNC16(sbase + 8192 + so, (const char*)(g_vh + go));
        }
        asm volatile("cp.async.commit_group;");
    };

    int lo = qt0 - W; if (lo < 0) lo = 0;
    const int kt_begin = lo & ~63;
    const int nt = ((qt0 - kt_begin) >> 6) + 1;

    issue_kv(kt_begin, 0);

    const int arow = wid * 16 + (lane & 15);
    const uint32_t aswzQ = (uint32_t)((arow & 7) << 4);
    const uint32_t acol_hi = (uint32_t)((lane >> 4) << 4);

    const int r0 = qt0 + wid * 16 + (lane >> 2);
    const int r1 = r0 + 8;
    const int cbase = (lane & 3) * 2;

    // wait for Q + kv tile 0; hoist Q fragments into registers
    asm volatile("cp.async.wait_group 0;");
    __syncthreads();
    uint32_t qa[4][4];
#pragma unroll
    for (int kk = 0; kk < 4; ++kk) {
        uint32_t bc = ((uint32_t)(kk * 32) + acol_hi) ^ aswzQ;
        LDSM4(qa[kk], sb + ATT_QH + (uint32_t)(arow * 128) + bc);
    }

    float m0 = -1e30f, m1 = -1e30f, l0 = 0.f, l1 = 0.f;
    float o[8][4];
#pragma unroll
    for (int j = 0; j < 8; j++)
#pragma unroll
        for (int q = 0; q < 4; q++) o[j][q] = 0.f;

#pragma unroll 1
    for (int it = 0; it < nt; ++it) {
        const int kt0 = kt_begin + it * 64;

        if (it > 0) {
            asm volatile("cp.async.wait_group 0;");
            __syncthreads();
        }
        // prefetch next tile (overlaps compute below); barrier above
        // guarantees stage (it+1)&1 is no longer read by any warp.
        if (it + 1 < nt) issue_kv(kt0 + 64, (it + 1) & 1);

        const uint32_t kvb = sb + ATT_K + (it & 1) * ATT_STG;

        // ---- S = Q K^T (log2 domain), K fragments loaded per p-block
        float sa[8][4];
#pragma unroll
        for (int j = 0; j < 8; j++)
#pragma unroll
            for (int q = 0; q < 4; q++) sa[j][q] = 0.f;

        {
            const int grp = lane >> 3;
            const int krow_off = (grp >> 1) * 8 + (lane & 7);
            const uint32_t bc_off0 = (uint32_t)((grp & 1) * 16);
#pragma unroll
            for (int kk = 0; kk < 4; ++kk) {
                const uint32_t bc_off = (uint32_t)(kk * 32) + bc_off0;
#pragma unroll
                for (int p = 0; p < 4; p++) {
                    uint32_t kh[4];
                    int krow = p * 16 + krow_off;
                    uint32_t so = (uint32_t)(krow * 128) + (bc_off ^ ((uint32_t)(krow & 7) << 4));
                    LDSM4(kh, kvb + so);
                    MMAH(sa[2 * p],     qa[kk], kh[0], kh[1]);
                    MMAH(sa[2 * p + 1], qa[kk], kh[2], kh[3]);
                }
            }
        }

        // ---- online softmax (base-2); interior tiles skip masking
        const bool full = (kt0 + 63 <= qt0) && (qt0 + 63 - kt0 <= W);
        float rm0 = -1e30f, rm1 = -1e30f;
        if (full) {
#pragma unroll
            for (int j = 0; j < 8; j++) {
                rm0 = fmaxf(rm0, fmaxf(sa[j][0], sa[j][1]));
                rm1 = fmaxf(rm1, fmaxf(sa[j][2], sa[j][3]));
            }
        } else {
#pragma unroll
            for (int j = 0; j < 8; j++) {
                const int c0 = kt0 + j * 8 + cbase;
                const int c1 = c0 + 1;
                bool ok00 = (c0 <= r0) && (r0 - c0 <= W);
                bool ok01 = (c1 <= r0) && (r0 - c1 <= W);
                bool ok10 = (c0 <= r1) && (r1 - c0 <= W);
                bool ok11 = (c1 <= r1) && (r1 - c1 <= W);
                sa[j][0] = ok00 ? sa[j][0] : -1e30f;
                sa[j][1] = ok01 ? sa[j][1] : -1e30f;
                sa[j][2] = ok10 ? sa[j][2] : -1e30f;
                sa[j][3] = ok11 ? sa[j][3] : -1e30f;
                rm0 = fmaxf(rm0, fmaxf(sa[j][0], sa[j][1]));
                rm1 = fmaxf(rm1, fmaxf(sa[j][2], sa[j][3]));
            }
        }
#pragma unroll
        for (int off = 1; off <= 2; off <<= 1) {
            rm0 = fmaxf(rm0, __shfl_xor_sync(0xFFFFFFFFu, rm0, off));
            rm1 = fmaxf(rm1, __shfl_xor_sync(0xFFFFFFFFu, rm1, off));
        }
        const float mn0 = fmaxf(m0, rm0);
        const float mn1 = fmaxf(m1, rm1);
        const float corr0 = exp2a(m0 - mn0);
        const float corr1 = exp2a(m1 - mn1);
        m0 = mn0; m1 = mn1;

        float rs0 = 0.f, rs1 = 0.f;
        uint32_t aph[4][4];
#pragma unroll
        for (int p = 0; p < 4; p++) {
#pragma unroll
            for (int jl = 0; jl < 2; jl++) {
                const int j = 2 * p + jl;
                float p0 = exp2a(sa[j][0] - mn0);
                float p1 = exp2a(sa[j][1] - mn0);
                float p2 = exp2a(sa[j][2] - mn1);
                float p3 = exp2a(sa[j][3] - mn1);
                rs0 += p0 + p1;
                rs1 += p2 + p3;
                aph[p][2 * jl + 0] = packh2(p0, p1);
                aph[p][2 * jl + 1] = packh2(p2, p3);
            }
        }
#pragma unroll
        for (int off = 1; off <= 2; off <<= 1) {
            rs0 += __shfl_xor_sync(0xFFFFFFFFu, rs0, off);
            rs1 += __shfl_xor_sync(0xFFFFFFFFu, rs1, off);
        }
        l0 = l0 * corr0 + rs0;
        l1 = l1 * corr1 + rs1;

#pragma unroll
        for (int j = 0; j < 8; j++) {
            o[j][0] *= corr0; o[j][1] *= corr0;
            o[j][2] *= corr1; o[j][3] *= corr1;
        }

        // ---- O += P V
        const uint32_t vbase = kvb + 8192;
        {
            const int vrow_off = lane & 15;
            const uint32_t vcol_hi = (uint32_t)((lane >> 4) << 4);
#pragma unroll
            for (int kk = 0; kk < 4; ++kk) {
#pragma unroll
                for (int t = 0; t < 4; t++) {
                    uint32_t vh[4];
                    int vrow = kk * 16 + vrow_off;
                    uint32_t bc = ((uint32_t)(t * 32) + vcol_hi) ^ ((uint32_t)(vrow & 7) << 4);
                    LDSM4T(vh, vbase + (uint32_t)(vrow * 128) + bc);
                    MMAH(o[2 * t],     aph[kk], vh[0], vh[1]);
                    MMAH(o[2 * t + 1], aph[kk], vh[2], vh[3]);
                }
            }
        }
        // no end-of-loop barrier: top barrier of next iter protects stage reuse
    }

    // epilogue: normalize, write fp16 y
    const float i0 = 1.0f / l0;
    const float i1 = 1.0f / l1;
#pragma unroll
    for (int j = 0; j < 8; j++) {
        size_t col = hoff + j * 8 + cbase;
        size_t idx0 = (btok + r0) * Cz + col;
        size_t idx1 = (btok + r1) * Cz + col;
        *(__half2*)(g_yh + idx0) = __floats2half2_rn(o[j][0] * i0, o[j][1] * i0);
        *(__half2*)(g_yh + idx1) = __floats2half2_rn(o[j][2] * i1, o[j][3] * i1);
    }
}

// ---------------------------------------------------------------------------
extern "C" void kernel_launch(void* const* d_in, const int* in_sizes, int n_in,
                              void* d_out, int out_size)
{
    const float* x     = (const float*)d_in[0];
    const float* ve    = (const float*)d_in[1];
    const float* cosb  = (const float*)d_in[2];
    const float* sinb  = (const float*)d_in[3];
    const float* Wq    = (const float*)d_in[4];
    const float* Wk    = (const float*)d_in[5];
    const float* Wv    = (const float*)d_in[6];
    const float* Wproj = (const float*)d_in[7];
    const float* Wg    = (const float*)d_in[8];
    const int*   win   = (const int*)d_in[9];
    float* out = (float*)d_out;

    __half *qkvh, *xhi, *veh, *whi, *yh;
    cudaGetSymbolAddress((void**)&qkvh, g_qkvh);
    cudaGetSymbolAddress((void**)&xhi, g_xhi);
    cudaGetSymbolAddress((void**)&veh, g_veh);
    cudaGetSymbolAddress((void**)&whi, g_whi);
    cudaGetSymbolAddress((void**)&yh, g_yh);

    const int WW = Cz * Cz;
    const int n4x = TOKz * Cz / 4;
    const int n4w = WW / 4;
    const int n4tot = 2 * n4x + 4 * n4w;

    cvt_all<<<(n4tot + 255) / 256, 256>>>((const float4*)x, (const float4*)ve,
                                          (const float4*)Wq, (const float4*)Wk,
                                          (const float4*)Wv, (const float4*)Wproj,
                                          xhi, veh, whi, n4x, n4w);

    cudaFuncSetAttribute((const void*)gemm_mma<1>,
                         cudaFuncAttributeMaxDynamicSharedMemorySize, GSMEM);
    cudaFuncSetAttribute((const void*)gemm_mma<0>,
                         cudaFuncAttributeMaxDynamicSharedMemorySize, GSMEM);

    // fused QKV GEMM (fp16 out): B = [Wq;Wk;Wv], N = 2304
    gemm_mma<1><<<dim3(QKVN / 128, TOKz / 128), 256, GSMEM>>>(xhi, whi, qkvh, QKVN);

    rope_rms_gate_kernel<<<TOKz, 192>>>(x, cosb, sinb, Wg);

    cudaFuncSetAttribute(attn_mma, cudaFuncAttributeMaxDynamicSharedMemorySize, ATT_SMEM);
    attn_mma<<<dim3(Tz / 64, NHz, Bz), 128, ATT_SMEM>>>(win);

    // projection GEMM (fp32 out): A = y, B = Wproj
    gemm_mma<0><<<dim3(Cz / 128, TOKz / 128), 256, GSMEM>>>(yh, whi + 3 * WW, out, Cz);
}